// round 11
// baseline (speedup 1.0000x reference)
#include <cuda_runtime.h>
#include <cuda_fp16.h>
#include <math.h>
#include <stdint.h>

#define NNODES 200000
#define NEDGES 3200000
#define SCAN_BLK 512
#define SCAN_NB ((NNODES + SCAN_BLK - 1) / SCAN_BLK)   // 391

// ---------------- scratch (no allocations allowed) ----------------
__device__ __align__(256) int   d_degi[NNODES];
__device__ __align__(256) float d_dinv[NNODES];
__device__ __align__(256) int   d_csr[NEDGES];
__device__ __align__(256) int   d_rowptr[NNODES + 1];
__device__ __align__(256) int   d_cursor[NNODES];
__device__ __align__(256) int   d_bsum[SCAN_NB];
__device__ __align__(256) int   d_boff[SCAN_NB];
__device__ __align__(256) __half d_w1h[256 * 128];   // [k][n] fp16
__device__ __align__(256) __half d_w2h[128 * 64];    // [k][n] fp16
__device__ __align__(256) __half d_g1h[(size_t)NNODES * 128];
__device__ __align__(256) __half d_o1h[(size_t)NNODES * 128];
__device__ __align__(256) __half d_g2h[(size_t)NNODES * 64];
__device__ __align__(256) __half d_o2h[(size_t)NNODES * 64];
__device__ __align__(256) float d_g3[(size_t)NNODES * 8];
__device__ __align__(256) float d_o3[(size_t)NNODES * 8];
__device__ int d_is64;

// ---------------- PTX helpers (baseline ISA, sm_103-safe) -------------
__device__ __forceinline__ uint32_t smem_u32(const void* p) {
    uint32_t a;
    asm("{ .reg .u64 t; cvta.to.shared.u64 t, %1; cvt.u32.u64 %0, t; }"
        : "=r"(a) : "l"(p));
    return a;
}
__device__ __forceinline__ void ldmx4(uint32_t* r, uint32_t addr) {
    asm volatile("ldmatrix.sync.aligned.m8n8.x4.shared.b16 {%0,%1,%2,%3}, [%4];"
                 : "=r"(r[0]), "=r"(r[1]), "=r"(r[2]), "=r"(r[3]) : "r"(addr));
}
__device__ __forceinline__ void ldmx4t(uint32_t* r, uint32_t addr) {
    asm volatile("ldmatrix.sync.aligned.m8n8.x4.trans.shared.b16 {%0,%1,%2,%3}, [%4];"
                 : "=r"(r[0]), "=r"(r[1]), "=r"(r[2]), "=r"(r[3]) : "r"(addr));
}
__device__ __forceinline__ void mma16816f(float* d, const uint32_t* a, const uint32_t* b) {
    asm volatile("mma.sync.aligned.m16n8k16.row.col.f32.f16.f16.f32 "
                 "{%0,%1,%2,%3}, {%4,%5,%6,%7}, {%8,%9}, {%0,%1,%2,%3};"
                 : "+f"(d[0]), "+f"(d[1]), "+f"(d[2]), "+f"(d[3])
                 : "r"(a[0]), "r"(a[1]), "r"(a[2]), "r"(a[3]),
                   "r"(b[0]), "r"(b[1]));
}
__device__ __forceinline__ uint2 pack4h(float a, float b, float c, float d) {
    __half2 p0 = __floats2half2_rn(a, b);
    __half2 p1 = __floats2half2_rn(c, d);
    uint2 r;
    r.x = *(uint32_t*)&p0;
    r.y = *(uint32_t*)&p1;
    return r;
}

// ---------------- edge dtype detection ----------------
__global__ void k_detect(const int* __restrict__ ei32) {
    if (threadIdx.x == 0 && blockIdx.x == 0) {
        int zeros = 0;
#pragma unroll
        for (int i = 0; i < 64; i++)
            if (ei32[2 * i + 1] == 0) zeros++;
        d_is64 = (zeros >= 60) ? 1 : 0;
    }
}

__global__ void k_edge_prep(const void* __restrict__ ei) {   // degree over dst
    int e = blockIdx.x * blockDim.x + threadIdx.x;
    if (e >= NEDGES) return;
    int d = d_is64 ? (int)((const long long*)ei)[(size_t)NEDGES + e]
                   : ((const int*)ei)[NEDGES + e];
    atomicAdd(&d_degi[d], 1);
}

// ---------------- W1/W2 -> fp16 planes, [k][n] layout ----------------
__global__ void k_wprep(const float* __restrict__ W1, const float* __restrict__ W2) {
    int idx = blockIdx.x * blockDim.x + threadIdx.x;
    if (idx < 256 * 128) d_w1h[idx] = __float2half_rn(W1[idx]);
    if (idx < 128 * 64)  d_w2h[idx] = __float2half_rn(W2[idx]);
}

// ---------------- scan -> rowptr (+ fused dinv) ----------------
__global__ void k_scan1() {
    __shared__ int sh[SCAN_BLK];
    int i = blockIdx.x * SCAN_BLK + threadIdx.x;
    int v = (i < NNODES) ? d_degi[i] : 0;
    if (i < NNODES) d_dinv[i] = rsqrtf((float)(v + 1));   // fused dinv
    sh[threadIdx.x] = v;
    __syncthreads();
    int incl = v;
#pragma unroll
    for (int off = 1; off < SCAN_BLK; off <<= 1) {
        int add = (threadIdx.x >= off) ? sh[threadIdx.x - off] : 0;
        __syncthreads();
        incl += add;
        sh[threadIdx.x] = incl;
        __syncthreads();
    }
    if (i < NNODES) d_rowptr[i] = incl - v;
    if (threadIdx.x == SCAN_BLK - 1) d_bsum[blockIdx.x] = incl;
}
__global__ void k_scan2() {
    __shared__ int sh[SCAN_BLK];
    int t = threadIdx.x;
    int v = (t < SCAN_NB) ? d_bsum[t] : 0;
    sh[t] = v;
    __syncthreads();
    int incl = v;
#pragma unroll
    for (int off = 1; off < SCAN_BLK; off <<= 1) {
        int add = (t >= off) ? sh[t - off] : 0;
        __syncthreads();
        incl += add;
        sh[t] = incl;
        __syncthreads();
    }
    if (t < SCAN_NB) d_boff[t] = incl - v;
}
__global__ void k_scan3() {
    int i = blockIdx.x * blockDim.x + threadIdx.x;
    if (i < NNODES) {
        int r = d_rowptr[i] + d_boff[i / SCAN_BLK];
        d_rowptr[i] = r;
        d_cursor[i] = r;
    }
    if (i == 0) d_rowptr[NNODES] = NEDGES;
}
__global__ void k_csr_fill(const void* __restrict__ ei) {
    int e = blockIdx.x * blockDim.x + threadIdx.x;
    if (e >= NEDGES) return;
    int s, d;
    if (d_is64) {
        const long long* p = (const long long*)ei;
        s = (int)p[e];
        d = (int)p[(size_t)NEDGES + e];
    } else {
        const int* p = (const int*)ei;
        s = p[e];
        d = p[NEDGES + e];
    }
    int pos = atomicAdd(&d_cursor[d], 1);
    d_csr[pos] = s;
}

// ========== GEMM1: fp16 single-plane MMA, 128x128 tile, K=256 ==========
// g1h[row] = (fp16) dinv[row]*(latent@W1[0:256] + hist*W1[256] + subg*W1[257])
#define APAD 40
#define BPAD 136
__global__ void __launch_bounds__(256)
k_gemm1_mma(const float* __restrict__ A, const float* __restrict__ W1,
            const float* __restrict__ hist, const float* __restrict__ subg,
            __half* __restrict__ g) {
    __shared__ __align__(16) __half sA[128][APAD];
    __shared__ __align__(16) __half sB[32][BPAD];

    const int tid = threadIdx.x;
    const int wid = tid >> 5, lane = tid & 31;
    const int rowBase = blockIdx.x * 128;
    const int mbase = (wid >> 1) * 32;
    const int nbase = (wid & 1) * 64;

    float acc[2][8][4];
#pragma unroll
    for (int i = 0; i < 2; i++)
#pragma unroll
        for (int j = 0; j < 8; j++)
#pragma unroll
            for (int q = 0; q < 4; q++) acc[i][j][q] = 0.f;

    const int aRow = lane & 15, aK = (lane >> 4) * 8;
    const int bK = lane & 15, bN = (lane >> 4) * 8;

    float4 va[4];
    uint4 vb[2];

    auto loadA = [&](int k0) {
#pragma unroll
        for (int t = 0; t < 4; t++) {
            int idx = tid + t * 256;
            int m = idx >> 3, f4 = idx & 7;
            int row = rowBase + m;
            va[t] = make_float4(0.f, 0.f, 0.f, 0.f);
            if (row < NNODES)
                va[t] = *(const float4*)(A + (size_t)row * 256 + k0 + f4 * 4);
        }
    };
    auto loadB = [&](int k0) {
#pragma unroll
        for (int t = 0; t < 2; t++) {
            int idx = tid + t * 256;
            int k = idx >> 4, u = idx & 15;
            vb[t] = *(const uint4*)(d_w1h + (size_t)(k0 + k) * 128 + u * 8);
        }
    };
    auto stage = [&]() {
#pragma unroll
        for (int t = 0; t < 4; t++) {
            int idx = tid + t * 256;
            int m = idx >> 3, f4 = idx & 7;
            *(uint2*)&sA[m][f4 * 4] = pack4h(va[t].x, va[t].y, va[t].z, va[t].w);
        }
#pragma unroll
        for (int t = 0; t < 2; t++) {
            int idx = tid + t * 256;
            int k = idx >> 4, u = idx & 15;
            *(uint4*)&sB[k][u * 8] = vb[t];
        }
    };

    loadA(0);
    loadB(0);
    for (int c = 0; c < 8; c++) {
        stage();
        __syncthreads();
        if (c < 7) { loadA((c + 1) * 32); loadB((c + 1) * 32); }
#pragma unroll
        for (int ks = 0; ks < 32; ks += 16) {
            uint32_t a[2][4], b[4][4];
#pragma unroll
            for (int mt = 0; mt < 2; mt++)
                ldmx4(a[mt], smem_u32(&sA[mbase + mt * 16 + aRow][ks + aK]));
#pragma unroll
            for (int ng = 0; ng < 4; ng++)
                ldmx4t(b[ng], smem_u32(&sB[ks + bK][nbase + ng * 16 + bN]));
#pragma unroll
            for (int mt = 0; mt < 2; mt++)
#pragma unroll
                for (int ng = 0; ng < 4; ng++) {
                    mma16816f(acc[mt][ng * 2 + 0], a[mt], &b[ng][0]);
                    mma16816f(acc[mt][ng * 2 + 1], a[mt], &b[ng][2]);
                }
        }
        __syncthreads();
    }

#pragma unroll
    for (int mt = 0; mt < 2; mt++) {
        int r0 = rowBase + mbase + mt * 16 + (lane >> 2);
        int r1 = r0 + 8;
        float dv0 = 0.f, hv0 = 0.f, sv0 = 0.f, dv1 = 0.f, hv1 = 0.f, sv1 = 0.f;
        if (r0 < NNODES) { dv0 = d_dinv[r0]; hv0 = hist[r0]; sv0 = subg[r0]; }
        if (r1 < NNODES) { dv1 = d_dinv[r1]; hv1 = hist[r1]; sv1 = subg[r1]; }
#pragma unroll
        for (int nt = 0; nt < 8; nt++) {
            int col = nbase + nt * 8 + (lane & 3) * 2;
            float w2a = __ldg(&W1[(size_t)256 * 128 + col]);
            float w2b = __ldg(&W1[(size_t)256 * 128 + col + 1]);
            float w3a = __ldg(&W1[(size_t)257 * 128 + col]);
            float w3b = __ldg(&W1[(size_t)257 * 128 + col + 1]);
            if (r0 < NNODES) {
                float ox = (acc[mt][nt][0] + hv0 * w2a + sv0 * w3a) * dv0;
                float oy = (acc[mt][nt][1] + hv0 * w2b + sv0 * w3b) * dv0;
                *(__half2*)(g + (size_t)r0 * 128 + col) = __floats2half2_rn(ox, oy);
            }
            if (r1 < NNODES) {
                float ox = (acc[mt][nt][2] + hv1 * w2a + sv1 * w3a) * dv1;
                float oy = (acc[mt][nt][3] + hv1 * w2b + sv1 * w3b) * dv1;
                *(__half2*)(g + (size_t)r1 * 128 + col) = __floats2half2_rn(ox, oy);
            }
        }
    }
}

// -------- fp16 pull-gather -> fp16 out: F halves/row, GROUP=F/8 ------------
template<int F, int GROUP>
__global__ void k_gather_h(const __half* __restrict__ g, __half* __restrict__ o) {
    const int lane = threadIdx.x & 31;
    const int warp = (blockIdx.x * blockDim.x + threadIdx.x) >> 5;
    constexpr int NPW = 32 / GROUP;
    const int gid  = lane / GROUP;
    const int sub  = lane % GROUP;          // owns halves sub*8..sub*8+7
    const int base = gid * GROUP;
    const int node = warp * NPW + gid;
    const bool valid = node < NNODES;

    int beg = valid ? __ldg(&d_rowptr[node])     : 0;
    int end = valid ? __ldg(&d_rowptr[node + 1]) : 0;
    int len = end - beg;

    float acc[8];
#pragma unroll
    for (int j = 0; j < 8; j++) acc[j] = 0.f;

    auto addRow = [&](int ss) {
        uint4 q = __ldg((const uint4*)(g + (size_t)ss * F) + sub);
        float2 f0 = __half22float2(*(__half2*)&q.x);
        float2 f1 = __half22float2(*(__half2*)&q.y);
        float2 f2 = __half22float2(*(__half2*)&q.z);
        float2 f3 = __half22float2(*(__half2*)&q.w);
        acc[0] += f0.x; acc[1] += f0.y; acc[2] += f1.x; acc[3] += f1.y;
        acc[4] += f2.x; acc[5] += f2.y; acc[6] += f3.x; acc[7] += f3.y;
    };
    if (valid) addRow(node);             // self-loop

    int maxlen = len;
#pragma unroll
    for (int off = 16; off; off >>= 1)
        maxlen = max(maxlen, __shfl_xor_sync(0xffffffffu, maxlen, off));

    int s_pre = 0;
    for (int t = 0; t < maxlen; t++) {
        if ((t % GROUP) == 0) {
            int j = beg + t + sub;
            s_pre = (j < end) ? __ldg(&d_csr[j]) : 0;
        }
        int ss = __shfl_sync(0xffffffffu, s_pre, base + (t % GROUP));
        if (t < len) addRow(ss);
    }
    if (valid) {
        uint2 q0 = pack4h(acc[0], acc[1], acc[2], acc[3]);
        uint2 q1 = pack4h(acc[4], acc[5], acc[6], acc[7]);
        uint4 q;
        q.x = q0.x; q.y = q0.y; q.z = q1.x; q.w = q1.y;
        *((uint4*)(o + (size_t)node * F) + sub) = q;
    }
}

// ========== GEMM2: fp16 single-plane MMA, 128x64 tile, K=128 ==========
// g2h[row] = (fp16) dinv[row] * (relu(dinv*o1+b1) @ W2)
#define BPAD2 72
__global__ void __launch_bounds__(256)
k_gemm2_mma(const __half* __restrict__ A, const float* __restrict__ b1,
            __half* __restrict__ g) {
    __shared__ __align__(16) __half sA[128][APAD];
    __shared__ __align__(16) __half sB[32][BPAD2];

    const int tid = threadIdx.x;
    const int wid = tid >> 5, lane = tid & 31;
    const int rowBase = blockIdx.x * 128;
    const int mbase = wid * 16;

    float acc[8][4];
#pragma unroll
    for (int j = 0; j < 8; j++)
#pragma unroll
        for (int q = 0; q < 4; q++) acc[j][q] = 0.f;

    const int aRow = lane & 15, aK = (lane >> 4) * 8;
    const int bK = lane & 15, bN = (lane >> 4) * 8;

    uint4 va[2];       // 8 halves each
    uint4 vb;

    auto loadA = [&](int k0) {
#pragma unroll
        for (int t = 0; t < 2; t++) {
            int idx = tid + t * 256;       // 0..511
            int m = idx >> 2, f8 = idx & 3;
            int row = rowBase + m;
            va[t] = make_uint4(0, 0, 0, 0);
            if (row < NNODES)
                va[t] = *((const uint4*)(A + (size_t)row * 128) + (k0 >> 3) + f8);
        }
    };
    auto loadB = [&](int k0) {
        int k = tid >> 3, u = tid & 7;     // 256 uint4
        vb = *(const uint4*)(d_w2h + (size_t)(k0 + k) * 64 + u * 8);
    };
    auto stage = [&](int k0) {
#pragma unroll
        for (int t = 0; t < 2; t++) {
            int idx = tid + t * 256;
            int m = idx >> 2, f8 = idx & 3;
            int row = rowBase + m;
            float dv = (row < NNODES) ? d_dinv[row] : 0.f;
            int kk = k0 + f8 * 8;
            float2 f0 = __half22float2(*(__half2*)&va[t].x);
            float2 f1 = __half22float2(*(__half2*)&va[t].y);
            float2 f2 = __half22float2(*(__half2*)&va[t].z);
            float2 f3 = __half22float2(*(__half2*)&va[t].w);
            float r[8] = {f0.x, f0.y, f1.x, f1.y, f2.x, f2.y, f3.x, f3.y};
#pragma unroll
            for (int j = 0; j < 8; j++)
                r[j] = fmaxf(fmaf(dv, r[j], __ldg(&b1[kk + j])), 0.f);
            uint2 q0 = pack4h(r[0], r[1], r[2], r[3]);
            uint2 q1 = pack4h(r[4], r[5], r[6], r[7]);
            uint4 q;
            q.x = q0.x; q.y = q0.y; q.z = q1.x; q.w = q1.y;
            *(uint4*)&sA[m][f8 * 8] = q;
        }
        {
            int k = tid >> 3, u = tid & 7;
            *(uint4*)&sB[k][u * 8] = vb;
        }
    };

    loadA(0);
    loadB(0);
    for (int c = 0; c < 4; c++) {
        stage(c * 32);
        __syncthreads();
        if (c < 3) { loadA((c + 1) * 32); loadB((c + 1) * 32); }
#pragma unroll
        for (int ks = 0; ks < 32; ks += 16) {
            uint32_t a[4], b[4][4];
            ldmx4(a, smem_u32(&sA[mbase + aRow][ks + aK]));
#pragma unroll
            for (int ng = 0; ng < 4; ng++)
                ldmx4t(b[ng], smem_u32(&sB[ks + bK][ng * 16 + bN]));
#pragma unroll
            for (int ng = 0; ng < 4; ng++) {
                mma16816f(acc[ng * 2 + 0], a, &b[ng][0]);
                mma16816f(acc[ng * 2 + 1], a, &b[ng][2]);
            }
        }
        __syncthreads();
    }

    int r0 = rowBase + mbase + (lane >> 2);
    int r1 = r0 + 8;
    float dv0 = (r0 < NNODES) ? d_dinv[r0] : 0.f;
    float dv1 = (r1 < NNODES) ? d_dinv[r1] : 0.f;
#pragma unroll
    for (int nt = 0; nt < 8; nt++) {
        int col = nt * 8 + (lane & 3) * 2;
        if (r0 < NNODES)
            *(__half2*)(g + (size_t)r0 * 64 + col) =
                __floats2half2_rn(acc[nt][0] * dv0, acc[nt][1] * dv0);
        if (r1 < NNODES)
            *(__half2*)(g + (size_t)r1 * 64 + col) =
                __floats2half2_rn(acc[nt][2] * dv1, acc[nt][3] * dv1);
    }
}

// ------------- CSR pull-gather (fp32, layer 3) ----------
template<int F, int GROUP>
__global__ void k_gather(const float* __restrict__ g, float* __restrict__ o) {
    const int lane = threadIdx.x & 31;
    const int warp = (blockIdx.x * blockDim.x + threadIdx.x) >> 5;
    constexpr int NPW = 32 / GROUP;
    const int gid  = lane / GROUP;
    const int sub  = lane % GROUP;
    const int base = gid * GROUP;
    const int node = warp * NPW + gid;
    const bool valid = node < NNODES;

    int beg = valid ? __ldg(&d_rowptr[node])     : 0;
    int end = valid ? __ldg(&d_rowptr[node + 1]) : 0;
    int len = end - beg;

    float4 acc = make_float4(0.f, 0.f, 0.f, 0.f);
    if (valid)
        acc = __ldg((const float4*)(g + (size_t)node * F) + sub);

    int maxlen = len;
#pragma unroll
    for (int off = 16; off; off >>= 1)
        maxlen = max(maxlen, __shfl_xor_sync(0xffffffffu, maxlen, off));

    int s_pre = 0;
    for (int t = 0; t < maxlen; t++) {
        if ((t % GROUP) == 0) {
            int j = beg + t + sub;
            s_pre = (j < end) ? __ldg(&d_csr[j]) : 0;
        }
        int ss = __shfl_sync(0xffffffffu, s_pre, base + (t % GROUP));
        if (t < len) {
            float4 v = __ldg((const float4*)(g + (size_t)ss * F) + sub);
            acc.x += v.x; acc.y += v.y; acc.z += v.z; acc.w += v.w;
        }
    }
    if (valid)
        *((float4*)(o + (size_t)node * F) + sub) = acc;
}

// ------- layer 3 GEMM: relu(dinv*o2+b2) @ W3, fused dinv, fp16 input ------
__global__ void __launch_bounds__(256) k_gemm3(const float* __restrict__ W3,
                                               const float* __restrict__ b2) {
    __shared__ float Ws[64 * 8];
    __shared__ float Bb[64];
    __shared__ __align__(16) float Hs[32][65];
    int tid = threadIdx.x;
    for (int i = tid; i < 512; i += 256) Ws[i] = W3[i];
    if (tid < 64) Bb[tid] = b2[tid];
    int nodeBase = blockIdx.x * 32;
    __syncthreads();
    {
        int r = tid >> 3, u = tid & 7;      // 32 rows x 8 uint4
        int node = nodeBase + r;
        if (node < NNODES) {
            float dv = d_dinv[node];
            uint4 q = *((const uint4*)(d_o2h + (size_t)node * 64) + u);
            float2 f0 = __half22float2(*(__half2*)&q.x);
            float2 f1 = __half22float2(*(__half2*)&q.y);
            float2 f2 = __half22float2(*(__half2*)&q.z);
            float2 f3 = __half22float2(*(__half2*)&q.w);
            float rr[8] = {f0.x, f0.y, f1.x, f1.y, f2.x, f2.y, f3.x, f3.y};
#pragma unroll
            for (int j = 0; j < 8; j++)
                Hs[r][u * 8 + j] = fmaxf(fmaf(dv, rr[j], Bb[u * 8 + j]), 0.f);
        } else {
#pragma unroll
            for (int j = 0; j < 8; j++) Hs[r][u * 8 + j] = 0.f;
        }
    }
    __syncthreads();
    int ln = tid / 8, col = tid % 8;
    int node = nodeBase + ln;
    if (node >= NNODES) return;
    float acc = 0.f;
#pragma unroll
    for (int k = 0; k < 64; k++) acc = fmaf(Hs[ln][k], Ws[k * 8 + col], acc);
    d_g3[(size_t)node * 8 + col] = d_dinv[node] * acc;
}

// ---------------- final head ----------------
__global__ void k_head(const float* __restrict__ Wc, const float* __restrict__ bc,
                       const float* __restrict__ b3, float* __restrict__ out) {
    int n = blockIdx.x * blockDim.x + threadIdx.x;
    if (n >= NNODES) return;
    float dv = d_dinv[n];
    float4 p0 = *(const float4*)(d_o3 + (size_t)n * 8);
    float4 p1 = *(const float4*)(d_o3 + (size_t)n * 8 + 4);
    float h[8] = {p0.x, p0.y, p0.z, p0.w, p1.x, p1.y, p1.z, p1.w};
    float r0 = __ldg(&bc[0]), r1 = __ldg(&bc[1]), r2 = __ldg(&bc[2]);
#pragma unroll
    for (int j = 0; j < 8; j++) {
        float hv = fmaxf(fmaf(dv, h[j], __ldg(&b3[j])), 0.f);
        r0 = fmaf(hv, __ldg(&Wc[j * 3 + 0]), r0);
        r1 = fmaf(hv, __ldg(&Wc[j * 3 + 1]), r1);
        r2 = fmaf(hv, __ldg(&Wc[j * 3 + 2]), r2);
    }
    out[(size_t)n * 3 + 0] = r0;
    out[(size_t)n * 3 + 1] = r1;
    out[(size_t)n * 3 + 2] = r2;
}

// ---------------- launch ----------------
extern "C" void kernel_launch(void* const* d_in, const int* in_sizes, int n_in,
                              void* d_out, int out_size) {
    const float* latent = (const float*)d_in[0];
    const float* hist   = (const float*)d_in[1];
    const float* subg   = (const float*)d_in[2];
    const void*  ei     = d_in[3];
    const float* W1 = (const float*)d_in[4];
    const float* b1 = (const float*)d_in[5];
    const float* W2 = (const float*)d_in[6];
    const float* b2 = (const float*)d_in[7];
    const float* W3 = (const float*)d_in[8];
    const float* b3 = (const float*)d_in[9];
    const float* Wc = (const float*)d_in[10];
    const float* bc = (const float*)d_in[11];
    float* out = (float*)d_out;

    __half *g1h, *o1h, *g2h, *o2h;
    float *g3, *o3;
    int* degi;
    cudaGetSymbolAddress((void**)&g1h, d_g1h);
    cudaGetSymbolAddress((void**)&o1h, d_o1h);
    cudaGetSymbolAddress((void**)&g2h, d_g2h);
    cudaGetSymbolAddress((void**)&o2h, d_o2h);
    cudaGetSymbolAddress((void**)&g3, d_g3);
    cudaGetSymbolAddress((void**)&o3, d_o3);
    cudaGetSymbolAddress((void**)&degi, d_degi);

    k_detect<<<1, 32>>>((const int*)ei);
    cudaMemsetAsync(degi, 0, NNODES * sizeof(int));
    k_edge_prep<<<(NEDGES + 255) / 256, 256>>>(ei);
    k_wprep<<<(256 * 128 + 255) / 256, 256>>>(W1, W2);
    k_scan1<<<SCAN_NB, SCAN_BLK>>>();                     // also computes dinv

    // GEMM1 on tensor cores (fp16 single-plane), fp16 output
    k_gemm1_mma<<<(NNODES + 127) / 128, 256>>>(latent, W1, hist, subg, g1h);

    // CSR build (remainder)
    k_scan2<<<1, SCAN_BLK>>>();
    k_scan3<<<(NNODES + 255) / 256, 256>>>();
    k_csr_fill<<<(NEDGES + 255) / 256, 256>>>(ei);

    // layer 1 aggregate (fp16 in/out, fp32 accumulate)
    k_gather_h<128, 16><<<(NNODES * 16 + 255) / 256, 256>>>(g1h, o1h);

    // layer 2 on tensor cores, fused relu(dinv*o1+b1), fp16 in/out
    k_gemm2_mma<<<(NNODES + 127) / 128, 256>>>(o1h, b1, g2h);
    k_gather_h<64, 8><<<(NNODES * 8 + 255) / 256, 256>>>(g2h, o2h);

    // layer 3: 64 -> 8
    k_gemm3<<<(NNODES + 31) / 32, 256>>>(W3, b2);
    k_gather<8, 2><<<(NNODES * 2 + 255) / 256, 256>>>(g3, o3);

    k_head<<<(NNODES + 255) / 256, 256>>>(Wc, bc, b3, out);
}

// round 12
// speedup vs baseline: 1.3672x; 1.3672x over previous
#include <cuda_runtime.h>
#include <cuda_fp16.h>
#include <math.h>
#include <stdint.h>

#define NNODES 200000
#define NEDGES 3200000
#define SCAN_BLK 512
#define SCAN_NB ((NNODES + SCAN_BLK - 1) / SCAN_BLK)   // 391

// ---------------- scratch (no allocations allowed) ----------------
__device__ __align__(256) int   d_degi[NNODES];
__device__ __align__(256) float d_dinv[NNODES];
__device__ __align__(256) int   d_csr[NEDGES];
__device__ __align__(256) int   d_rowptr[NNODES + 1];
__device__ __align__(256) int   d_cursor[NNODES];
__device__ __align__(256) int   d_bsum[SCAN_NB];
__device__ __align__(256) __half d_w1h[256 * 128];   // [k][n] fp16
__device__ __align__(256) __half d_w2h[128 * 64];    // [k][n] fp16
__device__ __align__(256) __half d_g1h[(size_t)NNODES * 128];
__device__ __align__(256) __half d_o1h[(size_t)NNODES * 128];
__device__ __align__(256) __half d_g2h[(size_t)NNODES * 64];
__device__ __align__(256) __half d_o2h[(size_t)NNODES * 64];
__device__ __align__(256) float d_g3[(size_t)NNODES * 8];
__device__ int d_is64;

// ---------------- PTX helpers (baseline ISA, sm_103-safe) -------------
__device__ __forceinline__ uint32_t smem_u32(const void* p) {
    uint32_t a;
    asm("{ .reg .u64 t; cvta.to.shared.u64 t, %1; cvt.u32.u64 %0, t; }"
        : "=r"(a) : "l"(p));
    return a;
}
__device__ __forceinline__ void ldmx4(uint32_t* r, uint32_t addr) {
    asm volatile("ldmatrix.sync.aligned.m8n8.x4.shared.b16 {%0,%1,%2,%3}, [%4];"
                 : "=r"(r[0]), "=r"(r[1]), "=r"(r[2]), "=r"(r[3]) : "r"(addr));
}
__device__ __forceinline__ void ldmx4t(uint32_t* r, uint32_t addr) {
    asm volatile("ldmatrix.sync.aligned.m8n8.x4.trans.shared.b16 {%0,%1,%2,%3}, [%4];"
                 : "=r"(r[0]), "=r"(r[1]), "=r"(r[2]), "=r"(r[3]) : "r"(addr));
}
__device__ __forceinline__ void mma16816f(float* d, const uint32_t* a, const uint32_t* b) {
    asm volatile("mma.sync.aligned.m16n8k16.row.col.f32.f16.f16.f32 "
                 "{%0,%1,%2,%3}, {%4,%5,%6,%7}, {%8,%9}, {%0,%1,%2,%3};"
                 : "+f"(d[0]), "+f"(d[1]), "+f"(d[2]), "+f"(d[3])
                 : "r"(a[0]), "r"(a[1]), "r"(a[2]), "r"(a[3]),
                   "r"(b[0]), "r"(b[1]));
}
__device__ __forceinline__ uint2 pack4h(float a, float b, float c, float d) {
    __half2 p0 = __floats2half2_rn(a, b);
    __half2 p1 = __floats2half2_rn(c, d);
    uint2 r;
    r.x = *(uint32_t*)&p0;
    r.y = *(uint32_t*)&p1;
    return r;
}

// ---------------- edge dtype detection ----------------
__global__ void k_detect(const int* __restrict__ ei32) {
    if (threadIdx.x == 0 && blockIdx.x == 0) {
        int zeros = 0;
#pragma unroll
        for (int i = 0; i < 64; i++)
            if (ei32[2 * i + 1] == 0) zeros++;
        d_is64 = (zeros >= 60) ? 1 : 0;
    }
}

__global__ void k_edge_prep(const void* __restrict__ ei) {   // degree over dst
    int e = blockIdx.x * blockDim.x + threadIdx.x;
    if (e >= NEDGES) return;
    int d = d_is64 ? (int)((const long long*)ei)[(size_t)NEDGES + e]
                   : ((const int*)ei)[NEDGES + e];
    atomicAdd(&d_degi[d], 1);
}

// ---------------- W1/W2 -> fp16 planes, [k][n] layout ----------------
__global__ void k_wprep(const float* __restrict__ W1, const float* __restrict__ W2) {
    int idx = blockIdx.x * blockDim.x + threadIdx.x;
    if (idx < 256 * 128) d_w1h[idx] = __float2half_rn(W1[idx]);
    if (idx < 128 * 64)  d_w2h[idx] = __float2half_rn(W2[idx]);
}

// ---------------- scan -> rowptr (+ fused dinv) ----------------
__global__ void k_scan1() {
    __shared__ int sh[SCAN_BLK];
    int i = blockIdx.x * SCAN_BLK + threadIdx.x;
    int v = (i < NNODES) ? d_degi[i] : 0;
    if (i < NNODES) d_dinv[i] = rsqrtf((float)(v + 1));   // fused dinv
    sh[threadIdx.x] = v;
    __syncthreads();
    int incl = v;
#pragma unroll
    for (int off = 1; off < SCAN_BLK; off <<= 1) {
        int add = (threadIdx.x >= off) ? sh[threadIdx.x - off] : 0;
        __syncthreads();
        incl += add;
        sh[threadIdx.x] = incl;
        __syncthreads();
    }
    if (i < NNODES) d_rowptr[i] = incl - v;
    if (threadIdx.x == SCAN_BLK - 1) d_bsum[blockIdx.x] = incl;
}

// scan2+scan3 fused: each 256-node block computes its own bsum prefix
__global__ void k_scan23() {
    __shared__ int s_off;
    int b = blockIdx.x;
    int i = b * 256 + threadIdx.x;
    if (threadIdx.x < 32) {
        int nb = (b * 256) / SCAN_BLK;   // # of full scan blocks before this block
        int sum = 0;
        for (int j = threadIdx.x; j < nb; j += 32) sum += d_bsum[j];
#pragma unroll
        for (int off = 16; off; off >>= 1)
            sum += __shfl_xor_sync(0xffffffffu, sum, off);
        if (threadIdx.x == 0) s_off = sum;
    }
    __syncthreads();
    if (i < NNODES) {
        int r = d_rowptr[i] + s_off;
        d_rowptr[i] = r;
        d_cursor[i] = r;
    }
    if (i == 0) d_rowptr[NNODES] = NEDGES;
}

__global__ void k_csr_fill(const void* __restrict__ ei) {
    int e = blockIdx.x * blockDim.x + threadIdx.x;
    if (e >= NEDGES) return;
    int s, d;
    if (d_is64) {
        const long long* p = (const long long*)ei;
        s = (int)p[e];
        d = (int)p[(size_t)NEDGES + e];
    } else {
        const int* p = (const int*)ei;
        s = p[e];
        d = p[NEDGES + e];
    }
    int pos = atomicAdd(&d_cursor[d], 1);
    d_csr[pos] = s;
}

// ========== GEMM1: fp16 single-plane MMA, 128x128 tile, K=256 ==========
// g1h[row] = (fp16) dinv[row]*(latent@W1[0:256] + hist*W1[256] + subg*W1[257])
#define APAD 40
#define BPAD 136
__global__ void __launch_bounds__(256)
k_gemm1_mma(const float* __restrict__ A, const float* __restrict__ W1,
            const float* __restrict__ hist, const float* __restrict__ subg,
            __half* __restrict__ g) {
    __shared__ __align__(16) __half sA[128][APAD];
    __shared__ __align__(16) __half sB[32][BPAD];

    const int tid = threadIdx.x;
    const int wid = tid >> 5, lane = tid & 31;
    const int rowBase = blockIdx.x * 128;
    const int mbase = (wid >> 1) * 32;
    const int nbase = (wid & 1) * 64;

    float acc[2][8][4];
#pragma unroll
    for (int i = 0; i < 2; i++)
#pragma unroll
        for (int j = 0; j < 8; j++)
#pragma unroll
            for (int q = 0; q < 4; q++) acc[i][j][q] = 0.f;

    const int aRow = lane & 15, aK = (lane >> 4) * 8;
    const int bK = lane & 15, bN = (lane >> 4) * 8;

    float4 va[4];
    uint4 vb[2];

    auto loadA = [&](int k0) {
#pragma unroll
        for (int t = 0; t < 4; t++) {
            int idx = tid + t * 256;
            int m = idx >> 3, f4 = idx & 7;
            int row = rowBase + m;
            va[t] = make_float4(0.f, 0.f, 0.f, 0.f);
            if (row < NNODES)
                va[t] = *(const float4*)(A + (size_t)row * 256 + k0 + f4 * 4);
        }
    };
    auto loadB = [&](int k0) {
#pragma unroll
        for (int t = 0; t < 2; t++) {
            int idx = tid + t * 256;
            int k = idx >> 4, u = idx & 15;
            vb[t] = *(const uint4*)(d_w1h + (size_t)(k0 + k) * 128 + u * 8);
        }
    };
    auto stage = [&]() {
#pragma unroll
        for (int t = 0; t < 4; t++) {
            int idx = tid + t * 256;
            int m = idx >> 3, f4 = idx & 7;
            *(uint2*)&sA[m][f4 * 4] = pack4h(va[t].x, va[t].y, va[t].z, va[t].w);
        }
#pragma unroll
        for (int t = 0; t < 2; t++) {
            int idx = tid + t * 256;
            int k = idx >> 4, u = idx & 15;
            *(uint4*)&sB[k][u * 8] = vb[t];
        }
    };

    loadA(0);
    loadB(0);
    for (int c = 0; c < 8; c++) {
        stage();
        __syncthreads();
        if (c < 7) { loadA((c + 1) * 32); loadB((c + 1) * 32); }
#pragma unroll
        for (int ks = 0; ks < 32; ks += 16) {
            uint32_t a[2][4], b[4][4];
#pragma unroll
            for (int mt = 0; mt < 2; mt++)
                ldmx4(a[mt], smem_u32(&sA[mbase + mt * 16 + aRow][ks + aK]));
#pragma unroll
            for (int ng = 0; ng < 4; ng++)
                ldmx4t(b[ng], smem_u32(&sB[ks + bK][nbase + ng * 16 + bN]));
#pragma unroll
            for (int mt = 0; mt < 2; mt++)
#pragma unroll
                for (int ng = 0; ng < 4; ng++) {
                    mma16816f(acc[mt][ng * 2 + 0], a[mt], &b[ng][0]);
                    mma16816f(acc[mt][ng * 2 + 1], a[mt], &b[ng][2]);
                }
        }
        __syncthreads();
    }

#pragma unroll
    for (int mt = 0; mt < 2; mt++) {
        int r0 = rowBase + mbase + mt * 16 + (lane >> 2);
        int r1 = r0 + 8;
        float dv0 = 0.f, hv0 = 0.f, sv0 = 0.f, dv1 = 0.f, hv1 = 0.f, sv1 = 0.f;
        if (r0 < NNODES) { dv0 = d_dinv[r0]; hv0 = hist[r0]; sv0 = subg[r0]; }
        if (r1 < NNODES) { dv1 = d_dinv[r1]; hv1 = hist[r1]; sv1 = subg[r1]; }
#pragma unroll
        for (int nt = 0; nt < 8; nt++) {
            int col = nbase + nt * 8 + (lane & 3) * 2;
            float w2a = __ldg(&W1[(size_t)256 * 128 + col]);
            float w2b = __ldg(&W1[(size_t)256 * 128 + col + 1]);
            float w3a = __ldg(&W1[(size_t)257 * 128 + col]);
            float w3b = __ldg(&W1[(size_t)257 * 128 + col + 1]);
            if (r0 < NNODES) {
                float ox = (acc[mt][nt][0] + hv0 * w2a + sv0 * w3a) * dv0;
                float oy = (acc[mt][nt][1] + hv0 * w2b + sv0 * w3b) * dv0;
                *(__half2*)(g + (size_t)r0 * 128 + col) = __floats2half2_rn(ox, oy);
            }
            if (r1 < NNODES) {
                float ox = (acc[mt][nt][2] + hv1 * w2a + sv1 * w3a) * dv1;
                float oy = (acc[mt][nt][3] + hv1 * w2b + sv1 * w3b) * dv1;
                *(__half2*)(g + (size_t)r1 * 128 + col) = __floats2half2_rn(ox, oy);
            }
        }
    }
}

// -------- fp16 pull-gather -> fp16 out: F halves/row, GROUP=F/8 ------------
template<int F, int GROUP>
__global__ void k_gather_h(const __half* __restrict__ g, __half* __restrict__ o) {
    const int lane = threadIdx.x & 31;
    const int warp = (blockIdx.x * blockDim.x + threadIdx.x) >> 5;
    constexpr int NPW = 32 / GROUP;
    const int gid  = lane / GROUP;
    const int sub  = lane % GROUP;          // owns halves sub*8..sub*8+7
    const int base = gid * GROUP;
    const int node = warp * NPW + gid;
    const bool valid = node < NNODES;

    int beg = valid ? __ldg(&d_rowptr[node])     : 0;
    int end = valid ? __ldg(&d_rowptr[node + 1]) : 0;
    int len = end - beg;

    float acc[8];
#pragma unroll
    for (int j = 0; j < 8; j++) acc[j] = 0.f;

    auto addRow = [&](int ss) {
        uint4 q = __ldg((const uint4*)(g + (size_t)ss * F) + sub);
        float2 f0 = __half22float2(*(__half2*)&q.x);
        float2 f1 = __half22float2(*(__half2*)&q.y);
        float2 f2 = __half22float2(*(__half2*)&q.z);
        float2 f3 = __half22float2(*(__half2*)&q.w);
        acc[0] += f0.x; acc[1] += f0.y; acc[2] += f1.x; acc[3] += f1.y;
        acc[4] += f2.x; acc[5] += f2.y; acc[6] += f3.x; acc[7] += f3.y;
    };
    if (valid) addRow(node);             // self-loop

    int maxlen = len;
#pragma unroll
    for (int off = 16; off; off >>= 1)
        maxlen = max(maxlen, __shfl_xor_sync(0xffffffffu, maxlen, off));

    int s_pre = 0;
    for (int t = 0; t < maxlen; t++) {
        if ((t % GROUP) == 0) {
            int j = beg + t + sub;
            s_pre = (j < end) ? __ldg(&d_csr[j]) : 0;
        }
        int ss = __shfl_sync(0xffffffffu, s_pre, base + (t % GROUP));
        if (t < len) addRow(ss);
    }
    if (valid) {
        uint2 q0 = pack4h(acc[0], acc[1], acc[2], acc[3]);
        uint2 q1 = pack4h(acc[4], acc[5], acc[6], acc[7]);
        uint4 q;
        q.x = q0.x; q.y = q0.y; q.z = q1.x; q.w = q1.y;
        *((uint4*)(o + (size_t)node * F) + sub) = q;
    }
}

// ========== GEMM2: fp16 single-plane MMA, 128x64 tile, K=128 ==========
// g2h[row] = (fp16) dinv[row] * (relu(dinv*o1+b1) @ W2)
#define BPAD2 72
__global__ void __launch_bounds__(256)
k_gemm2_mma(const __half* __restrict__ A, const float* __restrict__ b1,
            __half* __restrict__ g) {
    __shared__ __align__(16) __half sA[128][APAD];
    __shared__ __align__(16) __half sB[32][BPAD2];

    const int tid = threadIdx.x;
    const int wid = tid >> 5, lane = tid & 31;
    const int rowBase = blockIdx.x * 128;
    const int mbase = wid * 16;

    float acc[8][4];
#pragma unroll
    for (int j = 0; j < 8; j++)
#pragma unroll
        for (int q = 0; q < 4; q++) acc[j][q] = 0.f;

    const int aRow = lane & 15, aK = (lane >> 4) * 8;
    const int bK = lane & 15, bN = (lane >> 4) * 8;

    uint4 va[2];
    uint4 vb;

    auto loadA = [&](int k0) {
#pragma unroll
        for (int t = 0; t < 2; t++) {
            int idx = tid + t * 256;
            int m = idx >> 2, f8 = idx & 3;
            int row = rowBase + m;
            va[t] = make_uint4(0, 0, 0, 0);
            if (row < NNODES)
                va[t] = *((const uint4*)(A + (size_t)row * 128) + (k0 >> 3) + f8);
        }
    };
    auto loadB = [&](int k0) {
        int k = tid >> 3, u = tid & 7;
        vb = *(const uint4*)(d_w2h + (size_t)(k0 + k) * 64 + u * 8);
    };
    auto stage = [&](int k0) {
#pragma unroll
        for (int t = 0; t < 2; t++) {
            int idx = tid + t * 256;
            int m = idx >> 2, f8 = idx & 3;
            int row = rowBase + m;
            float dv = (row < NNODES) ? d_dinv[row] : 0.f;
            int kk = k0 + f8 * 8;
            float2 f0 = __half22float2(*(__half2*)&va[t].x);
            float2 f1 = __half22float2(*(__half2*)&va[t].y);
            float2 f2 = __half22float2(*(__half2*)&va[t].z);
            float2 f3 = __half22float2(*(__half2*)&va[t].w);
            float r[8] = {f0.x, f0.y, f1.x, f1.y, f2.x, f2.y, f3.x, f3.y};
#pragma unroll
            for (int j = 0; j < 8; j++)
                r[j] = fmaxf(fmaf(dv, r[j], __ldg(&b1[kk + j])), 0.f);
            uint2 q0 = pack4h(r[0], r[1], r[2], r[3]);
            uint2 q1 = pack4h(r[4], r[5], r[6], r[7]);
            uint4 q;
            q.x = q0.x; q.y = q0.y; q.z = q1.x; q.w = q1.y;
            *(uint4*)&sA[m][f8 * 8] = q;
        }
        {
            int k = tid >> 3, u = tid & 7;
            *(uint4*)&sB[k][u * 8] = vb;
        }
    };

    loadA(0);
    loadB(0);
    for (int c = 0; c < 4; c++) {
        stage(c * 32);
        __syncthreads();
        if (c < 3) { loadA((c + 1) * 32); loadB((c + 1) * 32); }
#pragma unroll
        for (int ks = 0; ks < 32; ks += 16) {
            uint32_t a[4], b[4][4];
            ldmx4(a, smem_u32(&sA[mbase + aRow][ks + aK]));
#pragma unroll
            for (int ng = 0; ng < 4; ng++)
                ldmx4t(b[ng], smem_u32(&sB[ks + bK][ng * 16 + bN]));
#pragma unroll
            for (int ng = 0; ng < 4; ng++) {
                mma16816f(acc[ng * 2 + 0], a, &b[ng][0]);
                mma16816f(acc[ng * 2 + 1], a, &b[ng][2]);
            }
        }
        __syncthreads();
    }

    int r0 = rowBase + mbase + (lane >> 2);
    int r1 = r0 + 8;
    float dv0 = (r0 < NNODES) ? d_dinv[r0] : 0.f;
    float dv1 = (r1 < NNODES) ? d_dinv[r1] : 0.f;
#pragma unroll
    for (int nt = 0; nt < 8; nt++) {
        int col = nt * 8 + (lane & 3) * 2;
        if (r0 < NNODES)
            *(__half2*)(g + (size_t)r0 * 64 + col) =
                __floats2half2_rn(acc[nt][0] * dv0, acc[nt][1] * dv0);
        if (r1 < NNODES)
            *(__half2*)(g + (size_t)r1 * 64 + col) =
                __floats2half2_rn(acc[nt][2] * dv1, acc[nt][3] * dv1);
    }
}

// ------- layer 3 GEMM: relu(dinv*o2+b2) @ W3, fused dinv, fp16 input ------
__global__ void __launch_bounds__(256) k_gemm3(const float* __restrict__ W3,
                                               const float* __restrict__ b2) {
    __shared__ float Ws[64 * 8];
    __shared__ float Bb[64];
    __shared__ __align__(16) float Hs[32][65];
    int tid = threadIdx.x;
    for (int i = tid; i < 512; i += 256) Ws[i] = W3[i];
    if (tid < 64) Bb[tid] = b2[tid];
    int nodeBase = blockIdx.x * 32;
    __syncthreads();
    {
        int r = tid >> 3, u = tid & 7;
        int node = nodeBase + r;
        if (node < NNODES) {
            float dv = d_dinv[node];
            uint4 q = *((const uint4*)(d_o2h + (size_t)node * 64) + u);
            float2 f0 = __half22float2(*(__half2*)&q.x);
            float2 f1 = __half22float2(*(__half2*)&q.y);
            float2 f2 = __half22float2(*(__half2*)&q.z);
            float2 f3 = __half22float2(*(__half2*)&q.w);
            float rr[8] = {f0.x, f0.y, f1.x, f1.y, f2.x, f2.y, f3.x, f3.y};
#pragma unroll
            for (int j = 0; j < 8; j++)
                Hs[r][u * 8 + j] = fmaxf(fmaf(dv, rr[j], Bb[u * 8 + j]), 0.f);
        } else {
#pragma unroll
            for (int j = 0; j < 8; j++) Hs[r][u * 8 + j] = 0.f;
        }
    }
    __syncthreads();
    int ln = tid / 8, col = tid % 8;
    int node = nodeBase + ln;
    if (node >= NNODES) return;
    float acc = 0.f;
#pragma unroll
    for (int k = 0; k < 64; k++) acc = fmaf(Hs[ln][k], Ws[k * 8 + col], acc);
    d_g3[(size_t)node * 8 + col] = d_dinv[node] * acc;
}

// ------- fused gather3 + head: out[n] = relu(dinv*(g3[n]+sum g3[src])+b3)@Wc+bc
__global__ void k_gather3_head(const float* __restrict__ Wc,
                               const float* __restrict__ bc,
                               const float* __restrict__ b3,
                               float* __restrict__ out) {
    const int lane = threadIdx.x & 31;
    const int warp = (blockIdx.x * blockDim.x + threadIdx.x) >> 5;
    const int gid  = lane >> 1;        // 16 nodes per warp
    const int sub  = lane & 1;         // owns cols sub*4..sub*4+3
    const int base = gid * 2;
    const int node = warp * 16 + gid;
    const bool valid = node < NNODES;

    int beg = valid ? __ldg(&d_rowptr[node])     : 0;
    int end = valid ? __ldg(&d_rowptr[node + 1]) : 0;
    int len = end - beg;

    float4 acc = make_float4(0.f, 0.f, 0.f, 0.f);
    if (valid)
        acc = __ldg((const float4*)(d_g3 + (size_t)node * 8) + sub);

    int maxlen = len;
#pragma unroll
    for (int off = 16; off; off >>= 1)
        maxlen = max(maxlen, __shfl_xor_sync(0xffffffffu, maxlen, off));

    int s_pre = 0;
    for (int t = 0; t < maxlen; t++) {
        if ((t & 1) == 0) {
            int j = beg + t + sub;
            s_pre = (j < end) ? __ldg(&d_csr[j]) : 0;
        }
        int ss = __shfl_sync(0xffffffffu, s_pre, base + (t & 1));
        if (t < len) {
            float4 v = __ldg((const float4*)(d_g3 + (size_t)ss * 8) + sub);
            acc.x += v.x; acc.y += v.y; acc.z += v.z; acc.w += v.w;
        }
    }

    // head: this lane's 4 features j = sub*4 .. sub*4+3
    float dv = valid ? d_dinv[node] : 0.f;
    float vals[4] = {acc.x, acc.y, acc.z, acc.w};
    float r0 = 0.f, r1 = 0.f, r2 = 0.f;
#pragma unroll
    for (int jj = 0; jj < 4; jj++) {
        int j = sub * 4 + jj;
        float hv = fmaxf(fmaf(dv, vals[jj], __ldg(&b3[j])), 0.f);
        r0 = fmaf(hv, __ldg(&Wc[j * 3 + 0]), r0);
        r1 = fmaf(hv, __ldg(&Wc[j * 3 + 1]), r1);
        r2 = fmaf(hv, __ldg(&Wc[j * 3 + 2]), r2);
    }
    r0 += __shfl_xor_sync(0xffffffffu, r0, 1);
    r1 += __shfl_xor_sync(0xffffffffu, r1, 1);
    r2 += __shfl_xor_sync(0xffffffffu, r2, 1);
    if (valid && sub == 0) {
        out[(size_t)node * 3 + 0] = r0 + __ldg(&bc[0]);
        out[(size_t)node * 3 + 1] = r1 + __ldg(&bc[1]);
        out[(size_t)node * 3 + 2] = r2 + __ldg(&bc[2]);
    }
}

// ---------------- launch ----------------
extern "C" void kernel_launch(void* const* d_in, const int* in_sizes, int n_in,
                              void* d_out, int out_size) {
    const float* latent = (const float*)d_in[0];
    const float* hist   = (const float*)d_in[1];
    const float* subg   = (const float*)d_in[2];
    const void*  ei     = d_in[3];
    const float* W1 = (const float*)d_in[4];
    const float* b1 = (const float*)d_in[5];
    const float* W2 = (const float*)d_in[6];
    const float* b2 = (const float*)d_in[7];
    const float* W3 = (const float*)d_in[8];
    const float* b3 = (const float*)d_in[9];
    const float* Wc = (const float*)d_in[10];
    const float* bc = (const float*)d_in[11];
    float* out = (float*)d_out;

    __half *g1h, *o1h, *g2h, *o2h;
    int* degi;
    cudaGetSymbolAddress((void**)&g1h, d_g1h);
    cudaGetSymbolAddress((void**)&o1h, d_o1h);
    cudaGetSymbolAddress((void**)&g2h, d_g2h);
    cudaGetSymbolAddress((void**)&o2h, d_o2h);
    cudaGetSymbolAddress((void**)&degi, d_degi);

    k_detect<<<1, 32>>>((const int*)ei);
    cudaMemsetAsync(degi, 0, NNODES * sizeof(int));
    k_edge_prep<<<(NEDGES + 255) / 256, 256>>>(ei);
    k_wprep<<<(256 * 128 + 255) / 256, 256>>>(W1, W2);
    k_scan1<<<SCAN_NB, SCAN_BLK>>>();                     // also computes dinv

    // GEMM1 on tensor cores (fp16 single-plane), fp16 output
    k_gemm1_mma<<<(NNODES + 127) / 128, 256>>>(latent, W1, hist, subg, g1h);

    // CSR build (remainder)
    k_scan23<<<(NNODES + 255) / 256, 256>>>();
    k_csr_fill<<<(NEDGES + 255) / 256, 256>>>(ei);

    // layer 1 aggregate (fp16 in/out, fp32 accumulate)
    k_gather_h<128, 16><<<(NNODES * 16 + 255) / 256, 256>>>(g1h, o1h);

    // layer 2 on tensor cores, fused relu(dinv*o1+b1), fp16 in/out
    k_gemm2_mma<<<(NNODES + 127) / 128, 256>>>(o1h, b1, g2h);
    k_gather_h<64, 8><<<(NNODES * 8 + 255) / 256, 256>>>(g2h, o2h);

    // layer 3: 64 -> 8, then fused gather+head
    k_gemm3<<<(NNODES + 31) / 32, 256>>>(W3, b2);
    k_gather3_head<<<(NNODES * 2 + 255) / 256, 256>>>(Wc, bc, b3, out);
}

// round 13
// speedup vs baseline: 1.4104x; 1.0316x over previous
#include <cuda_runtime.h>
#include <cuda_fp16.h>
#include <math.h>
#include <stdint.h>

#define NNODES 200000
#define NEDGES 3200000
#define SCAN_BLK 512
#define SCAN_NB ((NNODES + SCAN_BLK - 1) / SCAN_BLK)   // 391

// ---------------- scratch (no allocations allowed) ----------------
__device__ __align__(256) int   d_degi[NNODES];
__device__ __align__(256) float d_dinv[NNODES];
__device__ __align__(256) int   d_csr[NEDGES];
__device__ __align__(256) int   d_rowptr[NNODES + 1];
__device__ __align__(256) int   d_cursor[NNODES];
__device__ __align__(256) int   d_bsum[SCAN_NB];
__device__ __align__(256) __half d_w1h[256 * 128];   // [k][n] fp16
__device__ __align__(256) __half d_w2h[128 * 64];    // [k][n] fp16
__device__ __align__(256) __half d_g1h[(size_t)NNODES * 128];
__device__ __align__(256) __half d_o1h[(size_t)NNODES * 128];
__device__ __align__(256) __half d_g2h[(size_t)NNODES * 64];
__device__ __align__(256) __half d_o2h[(size_t)NNODES * 64];
__device__ __align__(256) float d_g3[(size_t)NNODES * 8];
__device__ int d_is64;

// ---------------- PTX helpers (baseline ISA, sm_103-safe) -------------
__device__ __forceinline__ uint32_t smem_u32(const void* p) {
    uint32_t a;
    asm("{ .reg .u64 t; cvta.to.shared.u64 t, %1; cvt.u32.u64 %0, t; }"
        : "=r"(a) : "l"(p));
    return a;
}
__device__ __forceinline__ void ldmx4(uint32_t* r, uint32_t addr) {
    asm volatile("ldmatrix.sync.aligned.m8n8.x4.shared.b16 {%0,%1,%2,%3}, [%4];"
                 : "=r"(r[0]), "=r"(r[1]), "=r"(r[2]), "=r"(r[3]) : "r"(addr));
}
__device__ __forceinline__ void ldmx4t(uint32_t* r, uint32_t addr) {
    asm volatile("ldmatrix.sync.aligned.m8n8.x4.trans.shared.b16 {%0,%1,%2,%3}, [%4];"
                 : "=r"(r[0]), "=r"(r[1]), "=r"(r[2]), "=r"(r[3]) : "r"(addr));
}
__device__ __forceinline__ void mma16816f(float* d, const uint32_t* a, const uint32_t* b) {
    asm volatile("mma.sync.aligned.m16n8k16.row.col.f32.f16.f16.f32 "
                 "{%0,%1,%2,%3}, {%4,%5,%6,%7}, {%8,%9}, {%0,%1,%2,%3};"
                 : "+f"(d[0]), "+f"(d[1]), "+f"(d[2]), "+f"(d[3])
                 : "r"(a[0]), "r"(a[1]), "r"(a[2]), "r"(a[3]),
                   "r"(b[0]), "r"(b[1]));
}
__device__ __forceinline__ uint2 pack4h(float a, float b, float c, float d) {
    __half2 p0 = __floats2half2_rn(a, b);
    __half2 p1 = __floats2half2_rn(c, d);
    uint2 r;
    r.x = *(uint32_t*)&p0;
    r.y = *(uint32_t*)&p1;
    return r;
}

// ---------------- edge dtype detection ----------------
__global__ void k_detect(const int* __restrict__ ei32) {
    if (threadIdx.x == 0 && blockIdx.x == 0) {
        int zeros = 0;
#pragma unroll
        for (int i = 0; i < 64; i++)
            if (ei32[2 * i + 1] == 0) zeros++;
        d_is64 = (zeros >= 60) ? 1 : 0;
    }
}

__global__ void k_edge_prep(const void* __restrict__ ei) {   // degree over dst
    int e = blockIdx.x * blockDim.x + threadIdx.x;
    if (e >= NEDGES) return;
    int d = d_is64 ? (int)((const long long*)ei)[(size_t)NEDGES + e]
                   : ((const int*)ei)[NEDGES + e];
    atomicAdd(&d_degi[d], 1);
}

// ---------------- W1/W2 -> fp16 planes, [k][n] layout ----------------
__global__ void k_wprep(const float* __restrict__ W1, const float* __restrict__ W2) {
    int idx = blockIdx.x * blockDim.x + threadIdx.x;
    if (idx < 256 * 128) d_w1h[idx] = __float2half_rn(W1[idx]);
    if (idx < 128 * 64)  d_w2h[idx] = __float2half_rn(W2[idx]);
}

// ---------------- scan -> rowptr (+ fused dinv) ----------------
__global__ void k_scan1() {
    __shared__ int sh[SCAN_BLK];
    int i = blockIdx.x * SCAN_BLK + threadIdx.x;
    int v = (i < NNODES) ? d_degi[i] : 0;
    if (i < NNODES) d_dinv[i] = rsqrtf((float)(v + 1));   // fused dinv
    sh[threadIdx.x] = v;
    __syncthreads();
    int incl = v;
#pragma unroll
    for (int off = 1; off < SCAN_BLK; off <<= 1) {
        int add = (threadIdx.x >= off) ? sh[threadIdx.x - off] : 0;
        __syncthreads();
        incl += add;
        sh[threadIdx.x] = incl;
        __syncthreads();
    }
    if (i < NNODES) d_rowptr[i] = incl - v;
    if (threadIdx.x == SCAN_BLK - 1) d_bsum[blockIdx.x] = incl;
}

// scan2+scan3 fused: each 256-node block computes its own bsum prefix
__global__ void k_scan23() {
    __shared__ int s_off;
    int b = blockIdx.x;
    int i = b * 256 + threadIdx.x;
    if (threadIdx.x < 32) {
        int nb = (b * 256) / SCAN_BLK;   // # of full scan blocks before this block
        int sum = 0;
        for (int j = threadIdx.x; j < nb; j += 32) sum += d_bsum[j];
#pragma unroll
        for (int off = 16; off; off >>= 1)
            sum += __shfl_xor_sync(0xffffffffu, sum, off);
        if (threadIdx.x == 0) s_off = sum;
    }
    __syncthreads();
    if (i < NNODES) {
        int r = d_rowptr[i] + s_off;
        d_rowptr[i] = r;
        d_cursor[i] = r;
    }
    if (i == 0) d_rowptr[NNODES] = NEDGES;
}

__global__ void k_csr_fill(const void* __restrict__ ei) {
    int e = blockIdx.x * blockDim.x + threadIdx.x;
    if (e >= NEDGES) return;
    int s, d;
    if (d_is64) {
        const long long* p = (const long long*)ei;
        s = (int)p[e];
        d = (int)p[(size_t)NEDGES + e];
    } else {
        const int* p = (const int*)ei;
        s = p[e];
        d = p[NEDGES + e];
    }
    int pos = atomicAdd(&d_cursor[d], 1);
    d_csr[pos] = s;
}

// ========== GEMM1: fp16 single-plane MMA, 128x128 tile, K=256 ==========
// g1h[row] = (fp16) dinv[row]*(latent@W1[0:256] + hist*W1[256] + subg*W1[257])
#define APAD 40
#define BPAD 136
__global__ void __launch_bounds__(256)
k_gemm1_mma(const float* __restrict__ A, const float* __restrict__ W1,
            const float* __restrict__ hist, const float* __restrict__ subg,
            __half* __restrict__ g) {
    __shared__ __align__(16) __half sA[128][APAD];
    __shared__ __align__(16) __half sB[32][BPAD];

    const int tid = threadIdx.x;
    const int wid = tid >> 5, lane = tid & 31;
    const int rowBase = blockIdx.x * 128;
    const int mbase = (wid >> 1) * 32;
    const int nbase = (wid & 1) * 64;

    float acc[2][8][4];
#pragma unroll
    for (int i = 0; i < 2; i++)
#pragma unroll
        for (int j = 0; j < 8; j++)
#pragma unroll
            for (int q = 0; q < 4; q++) acc[i][j][q] = 0.f;

    const int aRow = lane & 15, aK = (lane >> 4) * 8;
    const int bK = lane & 15, bN = (lane >> 4) * 8;

    float4 va[4];
    uint4 vb[2];

    auto loadA = [&](int k0) {
#pragma unroll
        for (int t = 0; t < 4; t++) {
            int idx = tid + t * 256;
            int m = idx >> 3, f4 = idx & 7;
            int row = rowBase + m;
            va[t] = make_float4(0.f, 0.f, 0.f, 0.f);
            if (row < NNODES)
                va[t] = *(const float4*)(A + (size_t)row * 256 + k0 + f4 * 4);
        }
    };
    auto loadB = [&](int k0) {
#pragma unroll
        for (int t = 0; t < 2; t++) {
            int idx = tid + t * 256;
            int k = idx >> 4, u = idx & 15;
            vb[t] = *(const uint4*)(d_w1h + (size_t)(k0 + k) * 128 + u * 8);
        }
    };
    auto stage = [&]() {
#pragma unroll
        for (int t = 0; t < 4; t++) {
            int idx = tid + t * 256;
            int m = idx >> 3, f4 = idx & 7;
            *(uint2*)&sA[m][f4 * 4] = pack4h(va[t].x, va[t].y, va[t].z, va[t].w);
        }
#pragma unroll
        for (int t = 0; t < 2; t++) {
            int idx = tid + t * 256;
            int k = idx >> 4, u = idx & 15;
            *(uint4*)&sB[k][u * 8] = vb[t];
        }
    };

    loadA(0);
    loadB(0);
    for (int c = 0; c < 8; c++) {
        stage();
        __syncthreads();
        if (c < 7) { loadA((c + 1) * 32); loadB((c + 1) * 32); }
#pragma unroll
        for (int ks = 0; ks < 32; ks += 16) {
            uint32_t a[2][4], b[4][4];
#pragma unroll
            for (int mt = 0; mt < 2; mt++)
                ldmx4(a[mt], smem_u32(&sA[mbase + mt * 16 + aRow][ks + aK]));
#pragma unroll
            for (int ng = 0; ng < 4; ng++)
                ldmx4t(b[ng], smem_u32(&sB[ks + bK][nbase + ng * 16 + bN]));
#pragma unroll
            for (int mt = 0; mt < 2; mt++)
#pragma unroll
                for (int ng = 0; ng < 4; ng++) {
                    mma16816f(acc[mt][ng * 2 + 0], a[mt], &b[ng][0]);
                    mma16816f(acc[mt][ng * 2 + 1], a[mt], &b[ng][2]);
                }
        }
        __syncthreads();
    }

#pragma unroll
    for (int mt = 0; mt < 2; mt++) {
        int r0 = rowBase + mbase + mt * 16 + (lane >> 2);
        int r1 = r0 + 8;
        float dv0 = 0.f, hv0 = 0.f, sv0 = 0.f, dv1 = 0.f, hv1 = 0.f, sv1 = 0.f;
        if (r0 < NNODES) { dv0 = d_dinv[r0]; hv0 = hist[r0]; sv0 = subg[r0]; }
        if (r1 < NNODES) { dv1 = d_dinv[r1]; hv1 = hist[r1]; sv1 = subg[r1]; }
#pragma unroll
        for (int nt = 0; nt < 8; nt++) {
            int col = nbase + nt * 8 + (lane & 3) * 2;
            float w2a = __ldg(&W1[(size_t)256 * 128 + col]);
            float w2b = __ldg(&W1[(size_t)256 * 128 + col + 1]);
            float w3a = __ldg(&W1[(size_t)257 * 128 + col]);
            float w3b = __ldg(&W1[(size_t)257 * 128 + col + 1]);
            if (r0 < NNODES) {
                float ox = (acc[mt][nt][0] + hv0 * w2a + sv0 * w3a) * dv0;
                float oy = (acc[mt][nt][1] + hv0 * w2b + sv0 * w3b) * dv0;
                *(__half2*)(g + (size_t)r0 * 128 + col) = __floats2half2_rn(ox, oy);
            }
            if (r1 < NNODES) {
                float ox = (acc[mt][nt][2] + hv1 * w2a + sv1 * w3a) * dv1;
                float oy = (acc[mt][nt][3] + hv1 * w2b + sv1 * w3b) * dv1;
                *(__half2*)(g + (size_t)r1 * 128 + col) = __floats2half2_rn(ox, oy);
            }
        }
    }
}

// -------- fp16 pull-gather -> fp16 out: F halves/row, GROUP=F/8 ------------
template<int F, int GROUP>
__global__ void k_gather_h(const __half* __restrict__ g, __half* __restrict__ o) {
    const int lane = threadIdx.x & 31;
    const int warp = (blockIdx.x * blockDim.x + threadIdx.x) >> 5;
    constexpr int NPW = 32 / GROUP;
    const int gid  = lane / GROUP;
    const int sub  = lane % GROUP;          // owns halves sub*8..sub*8+7
    const int base = gid * GROUP;
    const int node = warp * NPW + gid;
    const bool valid = node < NNODES;

    int beg = valid ? __ldg(&d_rowptr[node])     : 0;
    int end = valid ? __ldg(&d_rowptr[node + 1]) : 0;
    int len = end - beg;

    float acc[8];
#pragma unroll
    for (int j = 0; j < 8; j++) acc[j] = 0.f;

    auto addRow = [&](int ss) {
        uint4 q = __ldg((const uint4*)(g + (size_t)ss * F) + sub);
        float2 f0 = __half22float2(*(__half2*)&q.x);
        float2 f1 = __half22float2(*(__half2*)&q.y);
        float2 f2 = __half22float2(*(__half2*)&q.z);
        float2 f3 = __half22float2(*(__half2*)&q.w);
        acc[0] += f0.x; acc[1] += f0.y; acc[2] += f1.x; acc[3] += f1.y;
        acc[4] += f2.x; acc[5] += f2.y; acc[6] += f3.x; acc[7] += f3.y;
    };
    if (valid) addRow(node);             // self-loop

    int maxlen = len;
#pragma unroll
    for (int off = 16; off; off >>= 1)
        maxlen = max(maxlen, __shfl_xor_sync(0xffffffffu, maxlen, off));

    int s_pre = 0;
    for (int t = 0; t < maxlen; t++) {
        if ((t % GROUP) == 0) {
            int j = beg + t + sub;
            s_pre = (j < end) ? __ldg(&d_csr[j]) : 0;
        }
        int ss = __shfl_sync(0xffffffffu, s_pre, base + (t % GROUP));
        if (t < len) addRow(ss);
    }
    if (valid) {
        uint2 q0 = pack4h(acc[0], acc[1], acc[2], acc[3]);
        uint2 q1 = pack4h(acc[4], acc[5], acc[6], acc[7]);
        uint4 q;
        q.x = q0.x; q.y = q0.y; q.z = q1.x; q.w = q1.y;
        *((uint4*)(o + (size_t)node * F) + sub) = q;
    }
}

// ========== GEMM2: fp16 single-plane MMA, 128x64 tile, K=128 ==========
// g2h[row] = (fp16) dinv[row] * (relu(dinv*o1+b1) @ W2)
#define BPAD2 72
__global__ void __launch_bounds__(256)
k_gemm2_mma(const __half* __restrict__ A, const float* __restrict__ b1,
            __half* __restrict__ g) {
    __shared__ __align__(16) __half sA[128][APAD];
    __shared__ __align__(16) __half sB[32][BPAD2];

    const int tid = threadIdx.x;
    const int wid = tid >> 5, lane = tid & 31;
    const int rowBase = blockIdx.x * 128;
    const int mbase = wid * 16;

    float acc[8][4];
#pragma unroll
    for (int j = 0; j < 8; j++)
#pragma unroll
        for (int q = 0; q < 4; q++) acc[j][q] = 0.f;

    const int aRow = lane & 15, aK = (lane >> 4) * 8;
    const int bK = lane & 15, bN = (lane >> 4) * 8;

    uint4 va[2];
    uint4 vb;

    auto loadA = [&](int k0) {
#pragma unroll
        for (int t = 0; t < 2; t++) {
            int idx = tid + t * 256;
            int m = idx >> 2, f8 = idx & 3;
            int row = rowBase + m;
            va[t] = make_uint4(0, 0, 0, 0);
            if (row < NNODES)
                va[t] = *((const uint4*)(A + (size_t)row * 128) + (k0 >> 3) + f8);
        }
    };
    auto loadB = [&](int k0) {
        int k = tid >> 3, u = tid & 7;
        vb = *(const uint4*)(d_w2h + (size_t)(k0 + k) * 64 + u * 8);
    };
    auto stage = [&](int k0) {
#pragma unroll
        for (int t = 0; t < 2; t++) {
            int idx = tid + t * 256;
            int m = idx >> 2, f8 = idx & 3;
            int row = rowBase + m;
            float dv = (row < NNODES) ? d_dinv[row] : 0.f;
            int kk = k0 + f8 * 8;
            float2 f0 = __half22float2(*(__half2*)&va[t].x);
            float2 f1 = __half22float2(*(__half2*)&va[t].y);
            float2 f2 = __half22float2(*(__half2*)&va[t].z);
            float2 f3 = __half22float2(*(__half2*)&va[t].w);
            float r[8] = {f0.x, f0.y, f1.x, f1.y, f2.x, f2.y, f3.x, f3.y};
#pragma unroll
            for (int j = 0; j < 8; j++)
                r[j] = fmaxf(fmaf(dv, r[j], __ldg(&b1[kk + j])), 0.f);
            uint2 q0 = pack4h(r[0], r[1], r[2], r[3]);
            uint2 q1 = pack4h(r[4], r[5], r[6], r[7]);
            uint4 q;
            q.x = q0.x; q.y = q0.y; q.z = q1.x; q.w = q1.y;
            *(uint4*)&sA[m][f8 * 8] = q;
        }
        {
            int k = tid >> 3, u = tid & 7;
            *(uint4*)&sB[k][u * 8] = vb;
        }
    };

    loadA(0);
    loadB(0);
    for (int c = 0; c < 4; c++) {
        stage(c * 32);
        __syncthreads();
        if (c < 3) { loadA((c + 1) * 32); loadB((c + 1) * 32); }
#pragma unroll
        for (int ks = 0; ks < 32; ks += 16) {
            uint32_t a[4], b[4][4];
            ldmx4(a, smem_u32(&sA[mbase + aRow][ks + aK]));
#pragma unroll
            for (int ng = 0; ng < 4; ng++)
                ldmx4t(b[ng], smem_u32(&sB[ks + bK][ng * 16 + bN]));
#pragma unroll
            for (int ng = 0; ng < 4; ng++) {
                mma16816f(acc[ng * 2 + 0], a, &b[ng][0]);
                mma16816f(acc[ng * 2 + 1], a, &b[ng][2]);
            }
        }
        __syncthreads();
    }

    int r0 = rowBase + mbase + (lane >> 2);
    int r1 = r0 + 8;
    float dv0 = (r0 < NNODES) ? d_dinv[r0] : 0.f;
    float dv1 = (r1 < NNODES) ? d_dinv[r1] : 0.f;
#pragma unroll
    for (int nt = 0; nt < 8; nt++) {
        int col = nt * 8 + (lane & 3) * 2;
        if (r0 < NNODES)
            *(__half2*)(g + (size_t)r0 * 64 + col) =
                __floats2half2_rn(acc[nt][0] * dv0, acc[nt][1] * dv0);
        if (r1 < NNODES)
            *(__half2*)(g + (size_t)r1 * 64 + col) =
                __floats2half2_rn(acc[nt][2] * dv1, acc[nt][3] * dv1);
    }
}

// ------- layer 3 GEMM: relu(dinv*o2+b2) @ W3, fused dinv, fp16 input ------
__global__ void __launch_bounds__(256) k_gemm3(const float* __restrict__ W3,
                                               const float* __restrict__ b2) {
    __shared__ float Ws[64 * 8];
    __shared__ float Bb[64];
    __shared__ __align__(16) float Hs[32][65];
    int tid = threadIdx.x;
    for (int i = tid; i < 512; i += 256) Ws[i] = W3[i];
    if (tid < 64) Bb[tid] = b2[tid];
    int nodeBase = blockIdx.x * 32;
    __syncthreads();
    {
        int r = tid >> 3, u = tid & 7;
        int node = nodeBase + r;
        if (node < NNODES) {
            float dv = d_dinv[node];
            uint4 q = *((const uint4*)(d_o2h + (size_t)node * 64) + u);
            float2 f0 = __half22float2(*(__half2*)&q.x);
            float2 f1 = __half22float2(*(__half2*)&q.y);
            float2 f2 = __half22float2(*(__half2*)&q.z);
            float2 f3 = __half22float2(*(__half2*)&q.w);
            float rr[8] = {f0.x, f0.y, f1.x, f1.y, f2.x, f2.y, f3.x, f3.y};
#pragma unroll
            for (int j = 0; j < 8; j++)
                Hs[r][u * 8 + j] = fmaxf(fmaf(dv, rr[j], Bb[u * 8 + j]), 0.f);
        } else {
#pragma unroll
            for (int j = 0; j < 8; j++) Hs[r][u * 8 + j] = 0.f;
        }
    }
    __syncthreads();
    int ln = tid / 8, col = tid % 8;
    int node = nodeBase + ln;
    if (node >= NNODES) return;
    float acc = 0.f;
#pragma unroll
    for (int k = 0; k < 64; k++) acc = fmaf(Hs[ln][k], Ws[k * 8 + col], acc);
    d_g3[(size_t)node * 8 + col] = d_dinv[node] * acc;
}

// ------- fused gather3 + head: out[n] = relu(dinv*(g3[n]+sum g3[src])+b3)@Wc+bc
__global__ void k_gather3_head(const float* __restrict__ Wc,
                               const float* __restrict__ bc,
                               const float* __restrict__ b3,
                               float* __restrict__ out) {
    const int lane = threadIdx.x & 31;
    const int warp = (blockIdx.x * blockDim.x + threadIdx.x) >> 5;
    const int gid  = lane >> 1;        // 16 nodes per warp
    const int sub  = lane & 1;         // owns cols sub*4..sub*4+3
    const int base = gid * 2;
    const int node = warp * 16 + gid;
    const bool valid = node < NNODES;

    int beg = valid ? __ldg(&d_rowptr[node])     : 0;
    int end = valid ? __ldg(&d_rowptr[node + 1]) : 0;
    int len = end - beg;

    float4 acc = make_float4(0.f, 0.f, 0.f, 0.f);
    if (valid)
        acc = __ldg((const float4*)(d_g3 + (size_t)node * 8) + sub);

    int maxlen = len;
#pragma unroll
    for (int off = 16; off; off >>= 1)
        maxlen = max(maxlen, __shfl_xor_sync(0xffffffffu, maxlen, off));

    int s_pre = 0;
    for (int t = 0; t < maxlen; t++) {
        if ((t & 1) == 0) {
            int j = beg + t + sub;
            s_pre = (j < end) ? __ldg(&d_csr[j]) : 0;
        }
        int ss = __shfl_sync(0xffffffffu, s_pre, base + (t & 1));
        if (t < len) {
            float4 v = __ldg((const float4*)(d_g3 + (size_t)ss * 8) + sub);
            acc.x += v.x; acc.y += v.y; acc.z += v.z; acc.w += v.w;
        }
    }

    float dv = valid ? d_dinv[node] : 0.f;
    float vals[4] = {acc.x, acc.y, acc.z, acc.w};
    float r0 = 0.f, r1 = 0.f, r2 = 0.f;
#pragma unroll
    for (int jj = 0; jj < 4; jj++) {
        int j = sub * 4 + jj;
        float hv = fmaxf(fmaf(dv, vals[jj], __ldg(&b3[j])), 0.f);
        r0 = fmaf(hv, __ldg(&Wc[j * 3 + 0]), r0);
        r1 = fmaf(hv, __ldg(&Wc[j * 3 + 1]), r1);
        r2 = fmaf(hv, __ldg(&Wc[j * 3 + 2]), r2);
    }
    r0 += __shfl_xor_sync(0xffffffffu, r0, 1);
    r1 += __shfl_xor_sync(0xffffffffu, r1, 1);
    r2 += __shfl_xor_sync(0xffffffffu, r2, 1);
    if (valid && sub == 0) {
        out[(size_t)node * 3 + 0] = r0 + __ldg(&bc[0]);
        out[(size_t)node * 3 + 1] = r1 + __ldg(&bc[1]);
        out[(size_t)node * 3 + 2] = r2 + __ldg(&bc[2]);
    }
}

// ---------------- launch (dual-stream fork: gemm1 || CSR build) ------------
extern "C" void kernel_launch(void* const* d_in, const int* in_sizes, int n_in,
                              void* d_out, int out_size) {
    const float* latent = (const float*)d_in[0];
    const float* hist   = (const float*)d_in[1];
    const float* subg   = (const float*)d_in[2];
    const void*  ei     = d_in[3];
    const float* W1 = (const float*)d_in[4];
    const float* b1 = (const float*)d_in[5];
    const float* W2 = (const float*)d_in[6];
    const float* b2 = (const float*)d_in[7];
    const float* W3 = (const float*)d_in[8];
    const float* b3 = (const float*)d_in[9];
    const float* Wc = (const float*)d_in[10];
    const float* bc = (const float*)d_in[11];
    float* out = (float*)d_out;

    __half *g1h, *o1h, *g2h, *o2h;
    int* degi;
    cudaGetSymbolAddress((void**)&g1h, d_g1h);
    cudaGetSymbolAddress((void**)&o1h, d_o1h);
    cudaGetSymbolAddress((void**)&g2h, d_g2h);
    cudaGetSymbolAddress((void**)&o2h, d_o2h);
    cudaGetSymbolAddress((void**)&degi, d_degi);

    // one-time host resources (host-side only; no device memory involved)
    static cudaStream_t s2 = nullptr;
    static cudaEvent_t ev0 = nullptr, ev1 = nullptr, ev2 = nullptr;
    if (s2 == nullptr) {
        cudaStreamCreateWithFlags(&s2, cudaStreamNonBlocking);
        cudaEventCreateWithFlags(&ev0, cudaEventDisableTiming);
        cudaEventCreateWithFlags(&ev1, cudaEventDisableTiming);
        cudaEventCreateWithFlags(&ev2, cudaEventDisableTiming);
    }

    // main stream (0): detect -> memset -> edge_prep -> scan1
    k_detect<<<1, 32>>>((const int*)ei);
    cudaEventRecord(ev0, 0);
    cudaStreamWaitEvent(s2, ev0, 0);
    k_wprep<<<(256 * 128 + 255) / 256, 256, 0, s2>>>(W1, W2);   // overlaps prep

    cudaMemsetAsync(degi, 0, NNODES * sizeof(int));
    k_edge_prep<<<(NEDGES + 255) / 256, 256>>>(ei);
    k_scan1<<<SCAN_NB, SCAN_BLK>>>();                           // dinv ready

    // fork: gemm1 on s2 (needs dinv + w1h), CSR build continues on 0
    cudaEventRecord(ev1, 0);
    cudaStreamWaitEvent(s2, ev1, 0);
    k_gemm1_mma<<<(NNODES + 127) / 128, 256, 0, s2>>>(latent, W1, hist, subg, g1h);
    cudaEventRecord(ev2, s2);

    k_scan23<<<(NNODES + 255) / 256, 256>>>();
    k_csr_fill<<<(NEDGES + 255) / 256, 256>>>(ei);

    // join: gather1 needs csr (stream 0) AND g1h (s2)
    cudaStreamWaitEvent(0, ev2, 0);
    k_gather_h<128, 16><<<(NNODES * 16 + 255) / 256, 256>>>(g1h, o1h);

    // layer 2
    k_gemm2_mma<<<(NNODES + 127) / 128, 256>>>(o1h, b1, g2h);
    k_gather_h<64, 8><<<(NNODES * 8 + 255) / 256, 256>>>(g2h, o2h);

    // layer 3 + fused gather/head
    k_gemm3<<<(NNODES + 31) / 32, 256>>>(W3, b2);
    k_gather3_head<<<(NNODES * 2 + 255) / 256, 256>>>(Wc, bc, b3, out);
}

// round 14
// speedup vs baseline: 1.4495x; 1.0277x over previous
#include <cuda_runtime.h>
#include <cuda_fp16.h>
#include <math.h>
#include <stdint.h>

#define NNODES 200000
#define NEDGES 3200000
#define SCAN_BLK 512
#define SCAN_NB ((NNODES + SCAN_BLK - 1) / SCAN_BLK)   // 391

// ---------------- scratch (no allocations allowed) ----------------
__device__ __align__(256) int   d_degi[NNODES];
__device__ __align__(256) float d_dinv[NNODES];
__device__ __align__(256) int   d_csr[NEDGES];
__device__ __align__(256) int   d_rowptr[NNODES + 1];
__device__ __align__(256) int   d_cursor[NNODES];
__device__ __align__(256) int   d_bsum[SCAN_NB];
__device__ __align__(256) __half d_w1h[256 * 128];   // [k][n] fp16
__device__ __align__(256) __half d_w2h[128 * 64];    // [k][n] fp16
__device__ __align__(256) __half d_g1h[(size_t)NNODES * 128];
__device__ __align__(256) __half d_g2h[(size_t)NNODES * 64];
__device__ __align__(256) float d_g3[(size_t)NNODES * 8];
__device__ int d_is64;

// ---------------- PTX helpers (baseline ISA, sm_103-safe) -------------
__device__ __forceinline__ uint32_t smem_u32(const void* p) {
    uint32_t a;
    asm("{ .reg .u64 t; cvta.to.shared.u64 t, %1; cvt.u32.u64 %0, t; }"
        : "=r"(a) : "l"(p));
    return a;
}
__device__ __forceinline__ void ldmx4(uint32_t* r, uint32_t addr) {
    asm volatile("ldmatrix.sync.aligned.m8n8.x4.shared.b16 {%0,%1,%2,%3}, [%4];"
                 : "=r"(r[0]), "=r"(r[1]), "=r"(r[2]), "=r"(r[3]) : "r"(addr));
}
__device__ __forceinline__ void ldmx4t(uint32_t* r, uint32_t addr) {
    asm volatile("ldmatrix.sync.aligned.m8n8.x4.trans.shared.b16 {%0,%1,%2,%3}, [%4];"
                 : "=r"(r[0]), "=r"(r[1]), "=r"(r[2]), "=r"(r[3]) : "r"(addr));
}
__device__ __forceinline__ void mma16816f(float* d, const uint32_t* a, const uint32_t* b) {
    asm volatile("mma.sync.aligned.m16n8k16.row.col.f32.f16.f16.f32 "
                 "{%0,%1,%2,%3}, {%4,%5,%6,%7}, {%8,%9}, {%0,%1,%2,%3};"
                 : "+f"(d[0]), "+f"(d[1]), "+f"(d[2]), "+f"(d[3])
                 : "r"(a[0]), "r"(a[1]), "r"(a[2]), "r"(a[3]),
                   "r"(b[0]), "r"(b[1]));
}
__device__ __forceinline__ uint2 pack4h(float a, float b, float c, float d) {
    __half2 p0 = __floats2half2_rn(a, b);
    __half2 p1 = __floats2half2_rn(c, d);
    uint2 r;
    r.x = *(uint32_t*)&p0;
    r.y = *(uint32_t*)&p1;
    return r;
}

// ---------------- edge dtype detection ----------------
__global__ void k_detect(const int* __restrict__ ei32) {
    if (threadIdx.x == 0 && blockIdx.x == 0) {
        int zeros = 0;
#pragma unroll
        for (int i = 0; i < 64; i++)
            if (ei32[2 * i + 1] == 0) zeros++;
        d_is64 = (zeros >= 60) ? 1 : 0;
    }
}

__global__ void k_edge_prep(const void* __restrict__ ei) {   // degree over dst
    int e = blockIdx.x * blockDim.x + threadIdx.x;
    if (e >= NEDGES) return;
    int d = d_is64 ? (int)((const long long*)ei)[(size_t)NEDGES + e]
                   : ((const int*)ei)[NEDGES + e];
    atomicAdd(&d_degi[d], 1);
}

// ---------------- W1/W2 -> fp16 planes, [k][n] layout ----------------
__global__ void k_wprep(const float* __restrict__ W1, const float* __restrict__ W2) {
    int idx = blockIdx.x * blockDim.x + threadIdx.x;
    if (idx < 256 * 128) d_w1h[idx] = __float2half_rn(W1[idx]);
    if (idx < 128 * 64)  d_w2h[idx] = __float2half_rn(W2[idx]);
}

// ---------------- scan -> rowptr (+ fused dinv) ----------------
__global__ void k_scan1() {
    __shared__ int sh[SCAN_BLK];
    int i = blockIdx.x * SCAN_BLK + threadIdx.x;
    int v = (i < NNODES) ? d_degi[i] : 0;
    if (i < NNODES) d_dinv[i] = rsqrtf((float)(v + 1));   // fused dinv
    sh[threadIdx.x] = v;
    __syncthreads();
    int incl = v;
#pragma unroll
    for (int off = 1; off < SCAN_BLK; off <<= 1) {
        int add = (threadIdx.x >= off) ? sh[threadIdx.x - off] : 0;
        __syncthreads();
        incl += add;
        sh[threadIdx.x] = incl;
        __syncthreads();
    }
    if (i < NNODES) d_rowptr[i] = incl - v;
    if (threadIdx.x == SCAN_BLK - 1) d_bsum[blockIdx.x] = incl;
}

// scan2+scan3 fused
__global__ void k_scan23() {
    __shared__ int s_off;
    int b = blockIdx.x;
    int i = b * 256 + threadIdx.x;
    if (threadIdx.x < 32) {
        int nb = (b * 256) / SCAN_BLK;
        int sum = 0;
        for (int j = threadIdx.x; j < nb; j += 32) sum += d_bsum[j];
#pragma unroll
        for (int off = 16; off; off >>= 1)
            sum += __shfl_xor_sync(0xffffffffu, sum, off);
        if (threadIdx.x == 0) s_off = sum;
    }
    __syncthreads();
    if (i < NNODES) {
        int r = d_rowptr[i] + s_off;
        d_rowptr[i] = r;
        d_cursor[i] = r;
    }
    if (i == 0) d_rowptr[NNODES] = NEDGES;
}

__global__ void k_csr_fill(const void* __restrict__ ei) {
    int e = blockIdx.x * blockDim.x + threadIdx.x;
    if (e >= NEDGES) return;
    int s, d;
    if (d_is64) {
        const long long* p = (const long long*)ei;
        s = (int)p[e];
        d = (int)p[(size_t)NEDGES + e];
    } else {
        const int* p = (const int*)ei;
        s = p[e];
        d = p[NEDGES + e];
    }
    int pos = atomicAdd(&d_cursor[d], 1);
    d_csr[pos] = s;
}

// ========== GEMM1: fp16 single-plane MMA, 128x128 tile, K=256 ==========
#define APAD 40
#define BPAD 136
__global__ void __launch_bounds__(256)
k_gemm1_mma(const float* __restrict__ A, const float* __restrict__ W1,
            const float* __restrict__ hist, const float* __restrict__ subg,
            __half* __restrict__ g) {
    __shared__ __align__(16) __half sA[128][APAD];
    __shared__ __align__(16) __half sB[32][BPAD];

    const int tid = threadIdx.x;
    const int wid = tid >> 5, lane = tid & 31;
    const int rowBase = blockIdx.x * 128;
    const int mbase = (wid >> 1) * 32;
    const int nbase = (wid & 1) * 64;

    float acc[2][8][4];
#pragma unroll
    for (int i = 0; i < 2; i++)
#pragma unroll
        for (int j = 0; j < 8; j++)
#pragma unroll
            for (int q = 0; q < 4; q++) acc[i][j][q] = 0.f;

    const int aRow = lane & 15, aK = (lane >> 4) * 8;
    const int bK = lane & 15, bN = (lane >> 4) * 8;

    float4 va[4];
    uint4 vb[2];

    auto loadA = [&](int k0) {
#pragma unroll
        for (int t = 0; t < 4; t++) {
            int idx = tid + t * 256;
            int m = idx >> 3, f4 = idx & 7;
            int row = rowBase + m;
            va[t] = make_float4(0.f, 0.f, 0.f, 0.f);
            if (row < NNODES)
                va[t] = *(const float4*)(A + (size_t)row * 256 + k0 + f4 * 4);
        }
    };
    auto loadB = [&](int k0) {
#pragma unroll
        for (int t = 0; t < 2; t++) {
            int idx = tid + t * 256;
            int k = idx >> 4, u = idx & 15;
            vb[t] = *(const uint4*)(d_w1h + (size_t)(k0 + k) * 128 + u * 8);
        }
    };
    auto stage = [&]() {
#pragma unroll
        for (int t = 0; t < 4; t++) {
            int idx = tid + t * 256;
            int m = idx >> 3, f4 = idx & 7;
            *(uint2*)&sA[m][f4 * 4] = pack4h(va[t].x, va[t].y, va[t].z, va[t].w);
        }
#pragma unroll
        for (int t = 0; t < 2; t++) {
            int idx = tid + t * 256;
            int k = idx >> 4, u = idx & 15;
            *(uint4*)&sB[k][u * 8] = vb[t];
        }
    };

    loadA(0);
    loadB(0);
    for (int c = 0; c < 8; c++) {
        stage();
        __syncthreads();
        if (c < 7) { loadA((c + 1) * 32); loadB((c + 1) * 32); }
#pragma unroll
        for (int ks = 0; ks < 32; ks += 16) {
            uint32_t a[2][4], b[4][4];
#pragma unroll
            for (int mt = 0; mt < 2; mt++)
                ldmx4(a[mt], smem_u32(&sA[mbase + mt * 16 + aRow][ks + aK]));
#pragma unroll
            for (int ng = 0; ng < 4; ng++)
                ldmx4t(b[ng], smem_u32(&sB[ks + bK][nbase + ng * 16 + bN]));
#pragma unroll
            for (int mt = 0; mt < 2; mt++)
#pragma unroll
                for (int ng = 0; ng < 4; ng++) {
                    mma16816f(acc[mt][ng * 2 + 0], a[mt], &b[ng][0]);
                    mma16816f(acc[mt][ng * 2 + 1], a[mt], &b[ng][2]);
                }
        }
        __syncthreads();
    }

#pragma unroll
    for (int mt = 0; mt < 2; mt++) {
        int r0 = rowBase + mbase + mt * 16 + (lane >> 2);
        int r1 = r0 + 8;
        float dv0 = 0.f, hv0 = 0.f, sv0 = 0.f, dv1 = 0.f, hv1 = 0.f, sv1 = 0.f;
        if (r0 < NNODES) { dv0 = d_dinv[r0]; hv0 = hist[r0]; sv0 = subg[r0]; }
        if (r1 < NNODES) { dv1 = d_dinv[r1]; hv1 = hist[r1]; sv1 = subg[r1]; }
#pragma unroll
        for (int nt = 0; nt < 8; nt++) {
            int col = nbase + nt * 8 + (lane & 3) * 2;
            float w2a = __ldg(&W1[(size_t)256 * 128 + col]);
            float w2b = __ldg(&W1[(size_t)256 * 128 + col + 1]);
            float w3a = __ldg(&W1[(size_t)257 * 128 + col]);
            float w3b = __ldg(&W1[(size_t)257 * 128 + col + 1]);
            if (r0 < NNODES) {
                float ox = (acc[mt][nt][0] + hv0 * w2a + sv0 * w3a) * dv0;
                float oy = (acc[mt][nt][1] + hv0 * w2b + sv0 * w3b) * dv0;
                *(__half2*)(g + (size_t)r0 * 128 + col) = __floats2half2_rn(ox, oy);
            }
            if (r1 < NNODES) {
                float ox = (acc[mt][nt][2] + hv1 * w2a + sv1 * w3a) * dv1;
                float oy = (acc[mt][nt][3] + hv1 * w2b + sv1 * w3b) * dv1;
                *(__half2*)(g + (size_t)r1 * 128 + col) = __floats2half2_rn(ox, oy);
            }
        }
    }
}

// ===== FUSED gather1 + GEMM2: gather o1 rows into smem (relu/bias/dinv),
//       then 128x64 fp16 MMA. Output g2h. o1 never touches global memory. =====
#define A2PAD 136
#define BPAD2 72
__global__ void __launch_bounds__(256)
k_gather_gemm2(const __half* __restrict__ g1, const float* __restrict__ b1,
               __half* __restrict__ g2) {
    __shared__ __align__(16) __half sA[128][A2PAD];   // gathered+activated, K=128
    __shared__ __align__(16) __half sB[32][BPAD2];    // W2 chunk
    __shared__ float sb1[128];

    const int tid = threadIdx.x;
    const int wid = tid >> 5, lane = tid & 31;
    const int rowBase = blockIdx.x * 128;

    if (tid < 128) sb1[tid] = b1[tid];
    __syncthreads();

    // ---- phase 1: CSR pull-gather into sA (GROUP=16 lanes/node, 2 nodes/warp/pass)
    const int gid = lane >> 4;           // 0..1
    const int sub = lane & 15;           // owns halves sub*8..sub*8+7
    for (int pass = 0; pass < 8; pass++) {
        int local = pass * 16 + wid * 2 + gid;
        int node = rowBase + local;
        bool valid = node < NNODES;
        int beg = valid ? __ldg(&d_rowptr[node])     : 0;
        int end = valid ? __ldg(&d_rowptr[node + 1]) : 0;
        int len = end - beg;

        float acc[8];
#pragma unroll
        for (int j = 0; j < 8; j++) acc[j] = 0.f;
        auto addRow = [&](int ss) {
            uint4 q = __ldg((const uint4*)(g1 + (size_t)ss * 128) + sub);
            float2 f0 = __half22float2(*(__half2*)&q.x);
            float2 f1 = __half22float2(*(__half2*)&q.y);
            float2 f2 = __half22float2(*(__half2*)&q.z);
            float2 f3 = __half22float2(*(__half2*)&q.w);
            acc[0] += f0.x; acc[1] += f0.y; acc[2] += f1.x; acc[3] += f1.y;
            acc[4] += f2.x; acc[5] += f2.y; acc[6] += f3.x; acc[7] += f3.y;
        };
        if (valid) addRow(node);         // self-loop

        int maxlen = len;
#pragma unroll
        for (int off = 16; off; off >>= 1)
            maxlen = max(maxlen, __shfl_xor_sync(0xffffffffu, maxlen, off));

        int s_pre = 0;
        for (int t = 0; t < maxlen; t++) {
            if ((t & 15) == 0) {
                int j = beg + t + sub;
                s_pre = (j < end) ? __ldg(&d_csr[j]) : 0;
            }
            int ss = __shfl_sync(0xffffffffu, s_pre, gid * 16 + (t & 15));
            if (t < len) addRow(ss);
        }

        float dv = valid ? d_dinv[node] : 0.f;
#pragma unroll
        for (int j = 0; j < 8; j++)
            acc[j] = fmaxf(fmaf(dv, acc[j], sb1[sub * 8 + j]), 0.f);
        uint2 q0 = pack4h(acc[0], acc[1], acc[2], acc[3]);
        uint2 q1 = pack4h(acc[4], acc[5], acc[6], acc[7]);
        uint4 q;
        q.x = q0.x; q.y = q0.y; q.z = q1.x; q.w = q1.y;
        *(uint4*)&sA[local][sub * 8] = q;
    }

    // ---- phase 2: MMA (A resident in smem, B staged per 32-k chunk)
    const int mbase = wid * 16;
    const int aRow = lane & 15, aK = (lane >> 4) * 8;
    const int bK = lane & 15, bN = (lane >> 4) * 8;

    float acc[8][4];
#pragma unroll
    for (int j = 0; j < 8; j++)
#pragma unroll
        for (int q = 0; q < 4; q++) acc[j][q] = 0.f;

    for (int c = 0; c < 4; c++) {
        __syncthreads();
        {
            int k = tid >> 3, u = tid & 7;    // 32 rows x 8 uint4
            *(uint4*)&sB[k][u * 8] = *(const uint4*)(d_w2h + (size_t)(c * 32 + k) * 64 + u * 8);
        }
        __syncthreads();
#pragma unroll
        for (int ks = 0; ks < 32; ks += 16) {
            uint32_t a[4], b[4][4];
            ldmx4(a, smem_u32(&sA[mbase + aRow][c * 32 + ks + aK]));
#pragma unroll
            for (int ng = 0; ng < 4; ng++)
                ldmx4t(b[ng], smem_u32(&sB[ks + bK][ng * 16 + bN]));
#pragma unroll
            for (int ng = 0; ng < 4; ng++) {
                mma16816f(acc[ng * 2 + 0], a, &b[ng][0]);
                mma16816f(acc[ng * 2 + 1], a, &b[ng][2]);
            }
        }
    }

    int r0 = rowBase + mbase + (lane >> 2);
    int r1 = r0 + 8;
    float dv0 = (r0 < NNODES) ? d_dinv[r0] : 0.f;
    float dv1 = (r1 < NNODES) ? d_dinv[r1] : 0.f;
#pragma unroll
    for (int nt = 0; nt < 8; nt++) {
        int col = nt * 8 + (lane & 3) * 2;
        if (r0 < NNODES)
            *(__half2*)(g2 + (size_t)r0 * 64 + col) =
                __floats2half2_rn(acc[nt][0] * dv0, acc[nt][1] * dv0);
        if (r1 < NNODES)
            *(__half2*)(g2 + (size_t)r1 * 64 + col) =
                __floats2half2_rn(acc[nt][2] * dv1, acc[nt][3] * dv1);
    }
}

// ===== FUSED gather2 + GEMM3: gather o2 rows (relu/bias) into Hs, then
//       SIMT 64->8 GEMM with output dinv. o2 never touches global memory. =====
__global__ void __launch_bounds__(256)
k_gather_gemm3(const __half* __restrict__ g2, const float* __restrict__ W3,
               const float* __restrict__ b2) {
    __shared__ float Ws[64 * 8];
    __shared__ float Bb[64];
    __shared__ __align__(16) float Hs[32][65];
    const int tid = threadIdx.x;
    const int wid = tid >> 5, lane = tid & 31;
    const int nodeBase = blockIdx.x * 32;

    for (int i = tid; i < 512; i += 256) Ws[i] = W3[i];
    if (tid < 64) Bb[tid] = b2[tid];
    __syncthreads();

    // gather phase: GROUP=8 lanes/node, 4 nodes/warp, 8 warps -> 32 nodes
    {
        const int gid = lane >> 3;       // 0..3
        const int sub = lane & 7;        // owns halves sub*8..sub*8+7
        int local = wid * 4 + gid;       // 0..31
        int node = nodeBase + local;
        bool valid = node < NNODES;
        int beg = valid ? __ldg(&d_rowptr[node])     : 0;
        int end = valid ? __ldg(&d_rowptr[node + 1]) : 0;
        int len = end - beg;

        float acc[8];
#pragma unroll
        for (int j = 0; j < 8; j++) acc[j] = 0.f;
        auto addRow = [&](int ss) {
            uint4 q = __ldg((const uint4*)(g2 + (size_t)ss * 64) + sub);
            float2 f0 = __half22float2(*(__half2*)&q.x);
            float2 f1 = __half22float2(*(__half2*)&q.y);
            float2 f2 = __half22float2(*(__half2*)&q.z);
            float2 f3 = __half22float2(*(__half2*)&q.w);
            acc[0] += f0.x; acc[1] += f0.y; acc[2] += f1.x; acc[3] += f1.y;
            acc[4] += f2.x; acc[5] += f2.y; acc[6] += f3.x; acc[7] += f3.y;
        };
        if (valid) addRow(node);

        int maxlen = len;
#pragma unroll
        for (int off = 16; off; off >>= 1)
            maxlen = max(maxlen, __shfl_xor_sync(0xffffffffu, maxlen, off));

        int s_pre = 0;
        for (int t = 0; t < maxlen; t++) {
            if ((t & 7) == 0) {
                int j = beg + t + sub;
                s_pre = (j < end) ? __ldg(&d_csr[j]) : 0;
            }
            int ss = __shfl_sync(0xffffffffu, s_pre, gid * 8 + (t & 7));
            if (t < len) addRow(ss);
        }

        float dv = valid ? d_dinv[node] : 0.f;
#pragma unroll
        for (int j = 0; j < 8; j++)
            Hs[local][sub * 8 + j] = fmaxf(fmaf(dv, acc[j], Bb[sub * 8 + j]), 0.f);
    }
    __syncthreads();

    int ln = tid / 8, col = tid % 8;
    int node = nodeBase + ln;
    if (node >= NNODES) return;
    float acc = 0.f;
#pragma unroll
    for (int k = 0; k < 64; k++) acc = fmaf(Hs[ln][k], Ws[k * 8 + col], acc);
    d_g3[(size_t)node * 8 + col] = d_dinv[node] * acc;
}

// ------- fused gather3 + head ------
__global__ void k_gather3_head(const float* __restrict__ Wc,
                               const float* __restrict__ bc,
                               const float* __restrict__ b3,
                               float* __restrict__ out) {
    const int lane = threadIdx.x & 31;
    const int warp = (blockIdx.x * blockDim.x + threadIdx.x) >> 5;
    const int gid  = lane >> 1;
    const int sub  = lane & 1;
    const int base = gid * 2;
    const int node = warp * 16 + gid;
    const bool valid = node < NNODES;

    int beg = valid ? __ldg(&d_rowptr[node])     : 0;
    int end = valid ? __ldg(&d_rowptr[node + 1]) : 0;
    int len = end - beg;

    float4 acc = make_float4(0.f, 0.f, 0.f, 0.f);
    if (valid)
        acc = __ldg((const float4*)(d_g3 + (size_t)node * 8) + sub);

    int maxlen = len;
#pragma unroll
    for (int off = 16; off; off >>= 1)
        maxlen = max(maxlen, __shfl_xor_sync(0xffffffffu, maxlen, off));

    int s_pre = 0;
    for (int t = 0; t < maxlen; t++) {
        if ((t & 1) == 0) {
            int j = beg + t + sub;
            s_pre = (j < end) ? __ldg(&d_csr[j]) : 0;
        }
        int ss = __shfl_sync(0xffffffffu, s_pre, base + (t & 1));
        if (t < len) {
            float4 v = __ldg((const float4*)(d_g3 + (size_t)ss * 8) + sub);
            acc.x += v.x; acc.y += v.y; acc.z += v.z; acc.w += v.w;
        }
    }

    float dv = valid ? d_dinv[node] : 0.f;
    float vals[4] = {acc.x, acc.y, acc.z, acc.w};
    float r0 = 0.f, r1 = 0.f, r2 = 0.f;
#pragma unroll
    for (int jj = 0; jj < 4; jj++) {
        int j = sub * 4 + jj;
        float hv = fmaxf(fmaf(dv, vals[jj], __ldg(&b3[j])), 0.f);
        r0 = fmaf(hv, __ldg(&Wc[j * 3 + 0]), r0);
        r1 = fmaf(hv, __ldg(&Wc[j * 3 + 1]), r1);
        r2 = fmaf(hv, __ldg(&Wc[j * 3 + 2]), r2);
    }
    r0 += __shfl_xor_sync(0xffffffffu, r0, 1);
    r1 += __shfl_xor_sync(0xffffffffu, r1, 1);
    r2 += __shfl_xor_sync(0xffffffffu, r2, 1);
    if (valid && sub == 0) {
        out[(size_t)node * 3 + 0] = r0 + __ldg(&bc[0]);
        out[(size_t)node * 3 + 1] = r1 + __ldg(&bc[1]);
        out[(size_t)node * 3 + 2] = r2 + __ldg(&bc[2]);
    }
}

// ---------------- launch (dual-stream fork: gemm1 || CSR build) ------------
extern "C" void kernel_launch(void* const* d_in, const int* in_sizes, int n_in,
                              void* d_out, int out_size) {
    const float* latent = (const float*)d_in[0];
    const float* hist   = (const float*)d_in[1];
    const float* subg   = (const float*)d_in[2];
    const void*  ei     = d_in[3];
    const float* W1 = (const float*)d_in[4];
    const float* b1 = (const float*)d_in[5];
    const float* W2 = (const float*)d_in[6];
    const float* b2 = (const float*)d_in[7];
    const float* W3 = (const float*)d_in[8];
    const float* b3 = (const float*)d_in[9];
    const float* Wc = (const float*)d_in[10];
    const float* bc = (const float*)d_in[11];
    float* out = (float*)d_out;

    __half *g1h, *g2h;
    int* degi;
    cudaGetSymbolAddress((void**)&g1h, d_g1h);
    cudaGetSymbolAddress((void**)&g2h, d_g2h);
    cudaGetSymbolAddress((void**)&degi, d_degi);

    static cudaStream_t s2 = nullptr;
    static cudaEvent_t ev0 = nullptr, ev1 = nullptr, ev2 = nullptr;
    if (s2 == nullptr) {
        cudaStreamCreateWithFlags(&s2, cudaStreamNonBlocking);
        cudaEventCreateWithFlags(&ev0, cudaEventDisableTiming);
        cudaEventCreateWithFlags(&ev1, cudaEventDisableTiming);
        cudaEventCreateWithFlags(&ev2, cudaEventDisableTiming);
    }

    k_detect<<<1, 32>>>((const int*)ei);
    cudaEventRecord(ev0, 0);
    cudaStreamWaitEvent(s2, ev0, 0);
    k_wprep<<<(256 * 128 + 255) / 256, 256, 0, s2>>>(W1, W2);

    cudaMemsetAsync(degi, 0, NNODES * sizeof(int));
    k_edge_prep<<<(NEDGES + 255) / 256, 256>>>(ei);
    k_scan1<<<SCAN_NB, SCAN_BLK>>>();                           // dinv ready

    cudaEventRecord(ev1, 0);
    cudaStreamWaitEvent(s2, ev1, 0);
    k_gemm1_mma<<<(NNODES + 127) / 128, 256, 0, s2>>>(latent, W1, hist, subg, g1h);
    cudaEventRecord(ev2, s2);

    k_scan23<<<(NNODES + 255) / 256, 256>>>();
    k_csr_fill<<<(NEDGES + 255) / 256, 256>>>(ei);

    // join: fused gather1+gemm2 needs csr (stream 0) AND g1h (s2)
    cudaStreamWaitEvent(0, ev2, 0);
    k_gather_gemm2<<<(NNODES + 127) / 128, 256>>>(g1h, b1, g2h);

    // fused gather2+gemm3, then fused gather3+head
    k_gather_gemm3<<<(NNODES + 31) / 32, 256>>>(g2h, W3, b2);
    k_gather3_head<<<(NNODES * 2 + 255) / 256, 256>>>(Wc, bc, b3, out);
}